// round 1
// baseline (speedup 1.0000x reference)
#include <cuda_runtime.h>
#include <math.h>

// Problem constants
constexpr int Bc  = 2;
constexpr int Sc  = 2048;
constexpr int Dc  = 2048;
constexpr int Hc  = 16;
constexpr int DHc = 128;
constexpr int Mc  = Bc * Sc;   // 4096 rows for projections

// ---------------------------------------------------------------------------
// Scratch (device globals: allocation-free per harness rules)
// ---------------------------------------------------------------------------
__device__ float g_Q[(size_t)Mc * Dc];
__device__ float g_K[(size_t)Mc * Dc];
__device__ float g_V[(size_t)Mc * Dc];
__device__ float g_A[(size_t)Mc * Dc];   // attention output [b,s,h,dh]

// ---------------------------------------------------------------------------
// SGEMM:  C[M,N] = A[M,K] @ B[N,K]^T      (both row-major, K contiguous)
// BM=BN=128, BK=8, 256 threads, 8x8 microtile with 16-strided mapping.
// ---------------------------------------------------------------------------
__global__ void __launch_bounds__(256) sgemm_nt(const float* __restrict__ A,
                                                const float* __restrict__ B,
                                                float* __restrict__ C,
                                                int M, int N, int K) {
    __shared__ float As[8][128];
    __shared__ float Bs[8][128];

    const int tid = threadIdx.x;
    const int tx = tid & 15;
    const int ty = tid >> 4;
    const int m0 = blockIdx.y * 128;
    const int n0 = blockIdx.x * 128;

    float acc[8][8];
#pragma unroll
    for (int i = 0; i < 8; i++)
#pragma unroll
        for (int j = 0; j < 8; j++) acc[i][j] = 0.f;

    const int lr = tid >> 1;          // 0..127 row within tile
    const int lc = (tid & 1) * 4;     // 0 or 4
    const float* Aptr = A + (size_t)(m0 + lr) * K + lc;
    const float* Bptr = B + (size_t)(n0 + lr) * K + lc;

    for (int k0 = 0; k0 < K; k0 += 8) {
        float4 av = *(const float4*)(Aptr + k0);
        float4 bv = *(const float4*)(Bptr + k0);
        As[lc + 0][lr] = av.x; As[lc + 1][lr] = av.y;
        As[lc + 2][lr] = av.z; As[lc + 3][lr] = av.w;
        Bs[lc + 0][lr] = bv.x; Bs[lc + 1][lr] = bv.y;
        Bs[lc + 2][lr] = bv.z; Bs[lc + 3][lr] = bv.w;
        __syncthreads();

#pragma unroll
        for (int kk = 0; kk < 8; kk++) {
            float ar[8], br[8];
#pragma unroll
            for (int i = 0; i < 8; i++) {
                ar[i] = As[kk][ty + 16 * i];
                br[i] = Bs[kk][tx + 16 * i];
            }
#pragma unroll
            for (int i = 0; i < 8; i++)
#pragma unroll
                for (int j = 0; j < 8; j++)
                    acc[i][j] = fmaf(ar[i], br[j], acc[i][j]);
        }
        __syncthreads();
    }

#pragma unroll
    for (int i = 0; i < 8; i++) {
        size_t row = (size_t)(m0 + ty + 16 * i) * N + n0;
#pragma unroll
        for (int j = 0; j < 8; j++)
            C[row + tx + 16 * j] = acc[i][j];
    }
}

// ---------------------------------------------------------------------------
// RoPE (in-place on Q and K, selected by blockIdx.y). Layout [b,s,h,dh].
// cos/sin are [S, DH] with cos[dh] == cos[dh+64] by construction.
// ---------------------------------------------------------------------------
__global__ void rope_kernel(float* __restrict__ Q, float* __restrict__ K,
                            const float* __restrict__ cosp,
                            const float* __restrict__ sinp) {
    int i = blockIdx.x * blockDim.x + threadIdx.x;
    const int total = Bc * Sc * Hc * (DHc / 2);
    if (i >= total) return;
    int dh = i & 63;
    int h  = (i >> 6) & (Hc - 1);
    int bs = i >> 10;                 // /(64*16)
    int s  = bs & (Sc - 1);
    size_t base = (size_t)bs * Dc + h * DHc;

    float c  = cosp[s * DHc + dh];
    float sn = sinp[s * DHc + dh];
    float* p = blockIdx.y ? K : Q;
    float x1 = p[base + dh];
    float x2 = p[base + dh + 64];
    p[base + dh]      = x1 * c - x2 * sn;
    p[base + dh + 64] = x2 * c + x1 * sn;
}

// ---------------------------------------------------------------------------
// Flash attention (fp32, causal). BLOCK_M = BLOCK_N = 64, 256 threads.
// smem: sQ[64][129], sKV[64][129] (K then V), sS[64][65], stats[3*64].
// Thread (tx=tid%16, ty=tid/16): rows ty*4+i (i<4), cols tx+16*jj.
// ---------------------------------------------------------------------------
constexpr int FL_PAD   = 129;
constexpr int FS_PAD   = 65;
constexpr int FL_SMEMF = 2 * 64 * FL_PAD + 64 * FS_PAD + 3 * 64;

__global__ void __launch_bounds__(256) flash_kernel(const float* __restrict__ Q,
                                                    const float* __restrict__ K,
                                                    const float* __restrict__ V,
                                                    float* __restrict__ O) {
    extern __shared__ float smem[];
    float* sQ  = smem;
    float* sKV = sQ + 64 * FL_PAD;
    float* sS  = sKV + 64 * FL_PAD;
    float* sM  = sS + 64 * FS_PAD;
    float* sL  = sM + 64;
    float* sC  = sL + 64;

    const int tid = threadIdx.x;
    const int tx = tid & 15;
    const int ty = tid >> 4;
    const int qb = blockIdx.x;
    const int bh = blockIdx.y;
    const int b  = bh >> 4;
    const int h  = bh & (Hc - 1);
    const size_t base = ((size_t)b * Sc) * Dc + (size_t)h * DHc;
    const int q0 = qb * 64;
    const float scale = 0.08838834764831845f;   // 1/sqrt(128)

    // Load Q tile (64 x 128)
    for (int i = tid; i < 64 * 32; i += 256) {
        int r  = i >> 5;
        int c4 = (i & 31) << 2;
        float4 v = *(const float4*)(Q + base + (size_t)(q0 + r) * Dc + c4);
        float* d = sQ + r * FL_PAD + c4;
        d[0] = v.x; d[1] = v.y; d[2] = v.z; d[3] = v.w;
    }
    if (tid < 64) { sM[tid] = -1e30f; sL[tid] = 0.f; }

    float acc[4][8];
#pragma unroll
    for (int i = 0; i < 4; i++)
#pragma unroll
        for (int j = 0; j < 8; j++) acc[i][j] = 0.f;
    __syncthreads();

    for (int j = 0; j <= qb; ++j) {
        const int k0 = j * 64;

        // Load K tile
        for (int i = tid; i < 64 * 32; i += 256) {
            int r  = i >> 5;
            int c4 = (i & 31) << 2;
            float4 v = *(const float4*)(K + base + (size_t)(k0 + r) * Dc + c4);
            float* d = sKV + r * FL_PAD + c4;
            d[0] = v.x; d[1] = v.y; d[2] = v.z; d[3] = v.w;
        }
        __syncthreads();

        // S = scale * Q @ K^T   (64x64 tile)
        float sacc[4][4];
#pragma unroll
        for (int i = 0; i < 4; i++)
#pragma unroll
            for (int jj = 0; jj < 4; jj++) sacc[i][jj] = 0.f;

#pragma unroll 4
        for (int k = 0; k < 128; ++k) {
            float a[4], bb[4];
#pragma unroll
            for (int i = 0; i < 4; i++) a[i] = sQ[(ty * 4 + i) * FL_PAD + k];
#pragma unroll
            for (int jj = 0; jj < 4; jj++) bb[jj] = sKV[(tx + 16 * jj) * FL_PAD + k];
#pragma unroll
            for (int i = 0; i < 4; i++)
#pragma unroll
                for (int jj = 0; jj < 4; jj++)
                    sacc[i][jj] = fmaf(a[i], bb[jj], sacc[i][jj]);
        }

        const bool diag = (j == qb);
#pragma unroll
        for (int i = 0; i < 4; i++) {
            int row = ty * 4 + i;
#pragma unroll
            for (int jj = 0; jj < 4; jj++) {
                int col = tx + 16 * jj;
                float v = sacc[i][jj] * scale;
                if (diag && col > row) v = -1e30f;
                sS[row * FS_PAD + col] = v;
            }
        }
        __syncthreads();   // S done; everyone finished reading K

        // Load V tile into sKV (overwrite K)
        for (int i = tid; i < 64 * 32; i += 256) {
            int r  = i >> 5;
            int c4 = (i & 31) << 2;
            float4 v = *(const float4*)(V + base + (size_t)(k0 + r) * Dc + c4);
            float* d = sKV + r * FL_PAD + c4;
            d[0] = v.x; d[1] = v.y; d[2] = v.z; d[3] = v.w;
        }

        // Online softmax stats (one thread per row)
        if (tid < 64) {
            float* sr = sS + tid * FS_PAD;
            float mo = sM[tid];
            float m  = mo;
            for (int c = 0; c < 64; c++) m = fmaxf(m, sr[c]);
            float corr = __expf(mo - m);
            float lsum = 0.f;
            for (int c = 0; c < 64; c++) {
                float p = __expf(sr[c] - m);
                sr[c] = p;
                lsum += p;
            }
            sM[tid] = m;
            sL[tid] = sL[tid] * corr + lsum;
            sC[tid] = corr;
        }
        __syncthreads();

        // Rescale accumulator, then O += P @ V
        float cr[4];
#pragma unroll
        for (int i = 0; i < 4; i++) cr[i] = sC[ty * 4 + i];
#pragma unroll
        for (int i = 0; i < 4; i++)
#pragma unroll
            for (int jj = 0; jj < 8; jj++) acc[i][jj] *= cr[i];

#pragma unroll 4
        for (int kk = 0; kk < 64; ++kk) {
            float p[4], vv[8];
#pragma unroll
            for (int i = 0; i < 4; i++) p[i] = sS[(ty * 4 + i) * FS_PAD + kk];
#pragma unroll
            for (int jj = 0; jj < 8; jj++) vv[jj] = sKV[kk * FL_PAD + tx + 16 * jj];
#pragma unroll
            for (int i = 0; i < 4; i++)
#pragma unroll
                for (int jj = 0; jj < 8; jj++)
                    acc[i][jj] = fmaf(p[i], vv[jj], acc[i][jj]);
        }
        __syncthreads();   // before next iteration overwrites sKV / sS
    }

    // Normalize and write out: O[b, s, h, dh]
    float inv[4];
#pragma unroll
    for (int i = 0; i < 4; i++) inv[i] = 1.0f / sL[ty * 4 + i];
#pragma unroll
    for (int i = 0; i < 4; i++) {
        size_t row = base + (size_t)(q0 + ty * 4 + i) * Dc;
#pragma unroll
        for (int jj = 0; jj < 8; jj++)
            O[row + tx + 16 * jj] = acc[i][jj] * inv[i];
    }
}

// ---------------------------------------------------------------------------
// Launch
// ---------------------------------------------------------------------------
extern "C" void kernel_launch(void* const* d_in, const int* in_sizes, int n_in,
                              void* d_out, int out_size) {
    const float* x    = (const float*)d_in[0];
    const float* cosp = (const float*)d_in[1];
    const float* sinp = (const float*)d_in[2];
    const float* Wq   = (const float*)d_in[3];
    const float* Wk   = (const float*)d_in[4];
    const float* Wv   = (const float*)d_in[5];
    const float* Wo   = (const float*)d_in[6];
    float* out = (float*)d_out;

    float *Qb, *Kb, *Vb, *Ab;
    cudaGetSymbolAddress((void**)&Qb, g_Q);
    cudaGetSymbolAddress((void**)&Kb, g_K);
    cudaGetSymbolAddress((void**)&Vb, g_V);
    cudaGetSymbolAddress((void**)&Ab, g_A);

    dim3 ggrid(Dc / 128, Mc / 128);   // (16, 32)

    // QKV projections
    sgemm_nt<<<ggrid, 256>>>(x, Wq, Qb, Mc, Dc, Dc);
    sgemm_nt<<<ggrid, 256>>>(x, Wk, Kb, Mc, Dc, Dc);
    sgemm_nt<<<ggrid, 256>>>(x, Wv, Vb, Mc, Dc, Dc);

    // RoPE on Q and K
    {
        int total = Bc * Sc * Hc * (DHc / 2);
        dim3 rgrid((total + 255) / 256, 2);
        rope_kernel<<<rgrid, 256>>>(Qb, Kb, cosp, sinp);
    }

    // Flash attention
    {
        size_t smem = (size_t)FL_SMEMF * sizeof(float);
        cudaFuncSetAttribute(flash_kernel,
                             cudaFuncAttributeMaxDynamicSharedMemorySize,
                             (int)smem);
        dim3 fgrid(Sc / 64, Bc * Hc);   // (32, 32)
        flash_kernel<<<fgrid, 256, smem>>>(Qb, Kb, Vb, Ab);
    }

    // Output projection
    sgemm_nt<<<ggrid, 256>>>(Ab, Wo, out, Mc, Dc, Dc);
}

// round 2
// speedup vs baseline: 2.4708x; 2.4708x over previous
#include <cuda_runtime.h>
#include <math.h>
#include <stdint.h>

// Problem constants
constexpr int Bc  = 2;
constexpr int Sc  = 2048;
constexpr int Dc  = 2048;
constexpr int Hc  = 16;
constexpr int DHc = 128;
constexpr int Mc  = Bc * Sc;   // 4096 rows for projections

// ---------------------------------------------------------------------------
// Scratch (device globals: allocation-free per harness rules)
// ---------------------------------------------------------------------------
__device__ float g_Q [(size_t)Mc * Dc];
__device__ float g_K [(size_t)Mc * Dc];
__device__ float g_V [(size_t)Mc * Dc];
__device__ float g_A [(size_t)Mc * Dc];   // attention output [b,s,h,dh]
__device__ float g_xr[(size_t)Mc * Dc];   // tf32-rounded x
__device__ float g_Wq[(size_t)Dc * Dc];
__device__ float g_Wk[(size_t)Dc * Dc];
__device__ float g_Wv[(size_t)Dc * Dc];
__device__ float g_Wo[(size_t)Dc * Dc];

// ---------------------------------------------------------------------------
// Elementwise round-to-nearest tf32 (keeps GEMM hot loop convert-free and
// unbiased; truncation bias would compound over K=2048 and two chained GEMMs)
// ---------------------------------------------------------------------------
__global__ void round_tf32(const float* __restrict__ in, float* __restrict__ out,
                           int n4) {
    int i = blockIdx.x * blockDim.x + threadIdx.x;
    if (i >= n4) return;
    float4 v = *(const float4*)(in + (size_t)i * 4);
    uint32_t a, b, c, d;
    asm("cvt.rna.tf32.f32 %0, %1;" : "=r"(a) : "f"(v.x));
    asm("cvt.rna.tf32.f32 %0, %1;" : "=r"(b) : "f"(v.y));
    asm("cvt.rna.tf32.f32 %0, %1;" : "=r"(c) : "f"(v.z));
    asm("cvt.rna.tf32.f32 %0, %1;" : "=r"(d) : "f"(v.w));
    float4 o;
    o.x = __uint_as_float(a); o.y = __uint_as_float(b);
    o.z = __uint_as_float(c); o.w = __uint_as_float(d);
    *(float4*)(out + (size_t)i * 4) = o;
}

// ---------------------------------------------------------------------------
// tf32 mma.sync GEMM:  C[M,N] = A[M,K] @ B[N,K]^T   (row-major, K contiguous)
// BM=BN=128, BK=32, 256 thr = 8 warps (4 m x 2 n), warp tile 32x64,
// m16n8k8 atoms, cp.async double-buffered, smem stride 36 (conflict-free).
// ---------------------------------------------------------------------------
#define CP_ASYNC16(dst, src) \
    asm volatile("cp.async.cg.shared.global [%0], [%1], 16;\n" :: "r"(dst), "l"(src))

constexpr int GSTRIDE = 36;                       // floats per smem row
constexpr int GEMM_SMEM = 2 * 2 * 128 * GSTRIDE;  // floats (2 bufs x 2 mats)

__global__ void __launch_bounds__(256) gemm_tf32(const float* __restrict__ A,
                                                 const float* __restrict__ B,
                                                 float* __restrict__ C,
                                                 int M, int N, int K) {
    extern __shared__ float smem[];
    float* sA = smem;                      // [2][128][GSTRIDE]
    float* sB = smem + 2 * 128 * GSTRIDE;  // [2][128][GSTRIDE]

    const int tid  = threadIdx.x;
    const int wid  = tid >> 5;
    const int lane = tid & 31;
    const int wm = (wid & 3) * 32;     // warp m offset in tile
    const int wn = (wid >> 2) * 64;    // warp n offset in tile
    const int gp = lane >> 2;          // 0..7
    const int t4 = lane & 3;           // 0..3
    const int m0 = blockIdx.y * 128;
    const int n0 = blockIdx.x * 128;

    // global->smem load mapping: 32 rows x (8 x float4) per pass, 4 passes
    const int lrow = tid >> 3;         // 0..31
    const int lcol = (tid & 7) * 4;    // 0,4,..,28
    const float* Ag = A + (size_t)(m0 + lrow) * K + lcol;
    const float* Bg = B + (size_t)(n0 + lrow) * K + lcol;

    const uint32_t sA_u = (uint32_t)__cvta_generic_to_shared(sA);
    const uint32_t sB_u = (uint32_t)__cvta_generic_to_shared(sB);

    float acc[2][8][4];
#pragma unroll
    for (int im = 0; im < 2; im++)
#pragma unroll
        for (int in_ = 0; in_ < 8; in_++)
#pragma unroll
            for (int r = 0; r < 4; r++) acc[im][in_][r] = 0.f;

    const int nt = K / 32;

    // prefetch tile 0 into buffer 0
    {
#pragma unroll
        for (int p = 0; p < 4; p++) {
            uint32_t da = sA_u + (uint32_t)(((lrow + p * 32) * GSTRIDE + lcol) * 4);
            uint32_t db = sB_u + (uint32_t)(((lrow + p * 32) * GSTRIDE + lcol) * 4);
            CP_ASYNC16(da, Ag + (size_t)p * 32 * K);
            CP_ASYNC16(db, Bg + (size_t)p * 32 * K);
        }
        asm volatile("cp.async.commit_group;\n");
    }

    for (int kt = 0; kt < nt; kt++) {
        const int cur = kt & 1;
        if (kt + 1 < nt) {
            const int nb = cur ^ 1;
            const int k0 = (kt + 1) * 32;
#pragma unroll
            for (int p = 0; p < 4; p++) {
                uint32_t da = sA_u + (uint32_t)((((nb * 128) + lrow + p * 32) * GSTRIDE + lcol) * 4);
                uint32_t db = sB_u + (uint32_t)((((nb * 128) + lrow + p * 32) * GSTRIDE + lcol) * 4);
                CP_ASYNC16(da, Ag + (size_t)p * 32 * K + k0);
                CP_ASYNC16(db, Bg + (size_t)p * 32 * K + k0);
            }
            asm volatile("cp.async.commit_group;\n");
            asm volatile("cp.async.wait_group 1;\n");
        } else {
            asm volatile("cp.async.wait_group 0;\n");
        }
        __syncthreads();

        const float* cA = sA + cur * 128 * GSTRIDE;
        const float* cB = sB + cur * 128 * GSTRIDE;

#pragma unroll
        for (int ka = 0; ka < 4; ka++) {
            const int kk = ka * 8;
            uint32_t af[2][4];
#pragma unroll
            for (int im = 0; im < 2; im++) {
                const float* p = cA + (wm + im * 16 + gp) * GSTRIDE + kk + t4;
                af[im][0] = __float_as_uint(p[0]);
                af[im][1] = __float_as_uint(p[8 * GSTRIDE]);
                af[im][2] = __float_as_uint(p[4]);
                af[im][3] = __float_as_uint(p[8 * GSTRIDE + 4]);
            }
            uint32_t bf[8][2];
#pragma unroll
            for (int in_ = 0; in_ < 8; in_++) {
                const float* p = cB + (wn + in_ * 8 + gp) * GSTRIDE + kk + t4;
                bf[in_][0] = __float_as_uint(p[0]);
                bf[in_][1] = __float_as_uint(p[4]);
            }
#pragma unroll
            for (int im = 0; im < 2; im++)
#pragma unroll
                for (int in_ = 0; in_ < 8; in_++)
                    asm volatile(
                        "mma.sync.aligned.m16n8k8.row.col.f32.tf32.tf32.f32 "
                        "{%0,%1,%2,%3}, {%4,%5,%6,%7}, {%8,%9}, {%0,%1,%2,%3};\n"
                        : "+f"(acc[im][in_][0]), "+f"(acc[im][in_][1]),
                          "+f"(acc[im][in_][2]), "+f"(acc[im][in_][3])
                        : "r"(af[im][0]), "r"(af[im][1]),
                          "r"(af[im][2]), "r"(af[im][3]),
                          "r"(bf[in_][0]), "r"(bf[in_][1]));
        }
        __syncthreads();
    }

    // epilogue
#pragma unroll
    for (int im = 0; im < 2; im++) {
        const int mA = m0 + wm + im * 16 + gp;
#pragma unroll
        for (int in_ = 0; in_ < 8; in_++) {
            const int n = n0 + wn + in_ * 8 + 2 * t4;
            *(float2*)(C + (size_t)mA * N + n) =
                make_float2(acc[im][in_][0], acc[im][in_][1]);
            *(float2*)(C + (size_t)(mA + 8) * N + n) =
                make_float2(acc[im][in_][2], acc[im][in_][3]);
        }
    }
}

// ---------------------------------------------------------------------------
// RoPE (in-place on Q and K, selected by blockIdx.y). Layout [b,s,h,dh].
// ---------------------------------------------------------------------------
__global__ void rope_kernel(float* __restrict__ Q, float* __restrict__ K,
                            const float* __restrict__ cosp,
                            const float* __restrict__ sinp) {
    int i = blockIdx.x * blockDim.x + threadIdx.x;
    const int total = Bc * Sc * Hc * (DHc / 2);
    if (i >= total) return;
    int dh = i & 63;
    int h  = (i >> 6) & (Hc - 1);
    int bs = i >> 10;
    int s  = bs & (Sc - 1);
    size_t base = (size_t)bs * Dc + h * DHc;

    float c  = cosp[s * DHc + dh];
    float sn = sinp[s * DHc + dh];
    float* p = blockIdx.y ? K : Q;
    float x1 = p[base + dh];
    float x2 = p[base + dh + 64];
    p[base + dh]      = x1 * c - x2 * sn;
    p[base + dh + 64] = x2 * c + x1 * sn;
}

// ---------------------------------------------------------------------------
// Flash attention (fp32, causal). BLOCK_M = BLOCK_N = 64, 256 threads.
// ---------------------------------------------------------------------------
constexpr int FL_PAD   = 129;
constexpr int FS_PAD   = 65;
constexpr int FL_SMEMF = 2 * 64 * FL_PAD + 64 * FS_PAD + 3 * 64;

__global__ void __launch_bounds__(256) flash_kernel(const float* __restrict__ Q,
                                                    const float* __restrict__ K,
                                                    const float* __restrict__ V,
                                                    float* __restrict__ O) {
    extern __shared__ float smem[];
    float* sQ  = smem;
    float* sKV = sQ + 64 * FL_PAD;
    float* sS  = sKV + 64 * FL_PAD;
    float* sM  = sS + 64 * FS_PAD;
    float* sL  = sM + 64;
    float* sC  = sL + 64;

    const int tid = threadIdx.x;
    const int tx = tid & 15;
    const int ty = tid >> 4;
    const int qb = blockIdx.x;
    const int bh = blockIdx.y;
    const int b  = bh >> 4;
    const int h  = bh & (Hc - 1);
    const size_t base = ((size_t)b * Sc) * Dc + (size_t)h * DHc;
    const int q0 = qb * 64;
    const float scale = 0.08838834764831845f;   // 1/sqrt(128)

    for (int i = tid; i < 64 * 32; i += 256) {
        int r  = i >> 5;
        int c4 = (i & 31) << 2;
        float4 v = *(const float4*)(Q + base + (size_t)(q0 + r) * Dc + c4);
        float* d = sQ + r * FL_PAD + c4;
        d[0] = v.x; d[1] = v.y; d[2] = v.z; d[3] = v.w;
    }
    if (tid < 64) { sM[tid] = -1e30f; sL[tid] = 0.f; }

    float acc[4][8];
#pragma unroll
    for (int i = 0; i < 4; i++)
#pragma unroll
        for (int j = 0; j < 8; j++) acc[i][j] = 0.f;
    __syncthreads();

    for (int j = 0; j <= qb; ++j) {
        const int k0 = j * 64;

        for (int i = tid; i < 64 * 32; i += 256) {
            int r  = i >> 5;
            int c4 = (i & 31) << 2;
            float4 v = *(const float4*)(K + base + (size_t)(k0 + r) * Dc + c4);
            float* d = sKV + r * FL_PAD + c4;
            d[0] = v.x; d[1] = v.y; d[2] = v.z; d[3] = v.w;
        }
        __syncthreads();

        float sacc[4][4];
#pragma unroll
        for (int i = 0; i < 4; i++)
#pragma unroll
            for (int jj = 0; jj < 4; jj++) sacc[i][jj] = 0.f;

#pragma unroll 4
        for (int k = 0; k < 128; ++k) {
            float a[4], bb[4];
#pragma unroll
            for (int i = 0; i < 4; i++) a[i] = sQ[(ty * 4 + i) * FL_PAD + k];
#pragma unroll
            for (int jj = 0; jj < 4; jj++) bb[jj] = sKV[(tx + 16 * jj) * FL_PAD + k];
#pragma unroll
            for (int i = 0; i < 4; i++)
#pragma unroll
                for (int jj = 0; jj < 4; jj++)
                    sacc[i][jj] = fmaf(a[i], bb[jj], sacc[i][jj]);
        }

        const bool diag = (j == qb);
#pragma unroll
        for (int i = 0; i < 4; i++) {
            int row = ty * 4 + i;
#pragma unroll
            for (int jj = 0; jj < 4; jj++) {
                int col = tx + 16 * jj;
                float v = sacc[i][jj] * scale;
                if (diag && col > row) v = -1e30f;
                sS[row * FS_PAD + col] = v;
            }
        }
        __syncthreads();

        for (int i = tid; i < 64 * 32; i += 256) {
            int r  = i >> 5;
            int c4 = (i & 31) << 2;
            float4 v = *(const float4*)(V + base + (size_t)(k0 + r) * Dc + c4);
            float* d = sKV + r * FL_PAD + c4;
            d[0] = v.x; d[1] = v.y; d[2] = v.z; d[3] = v.w;
        }

        if (tid < 64) {
            float* sr = sS + tid * FS_PAD;
            float mo = sM[tid];
            float m  = mo;
            for (int c = 0; c < 64; c++) m = fmaxf(m, sr[c]);
            float corr = __expf(mo - m);
            float lsum = 0.f;
            for (int c = 0; c < 64; c++) {
                float p = __expf(sr[c] - m);
                sr[c] = p;
                lsum += p;
            }
            sM[tid] = m;
            sL[tid] = sL[tid] * corr + lsum;
            sC[tid] = corr;
        }
        __syncthreads();

        float cr[4];
#pragma unroll
        for (int i = 0; i < 4; i++) cr[i] = sC[ty * 4 + i];
#pragma unroll
        for (int i = 0; i < 4; i++)
#pragma unroll
            for (int jj = 0; jj < 8; jj++) acc[i][jj] *= cr[i];

#pragma unroll 4
        for (int kk = 0; kk < 64; ++kk) {
            float p[4], vv[8];
#pragma unroll
            for (int i = 0; i < 4; i++) p[i] = sS[(ty * 4 + i) * FS_PAD + kk];
#pragma unroll
            for (int jj = 0; jj < 8; jj++) vv[jj] = sKV[kk * FL_PAD + tx + 16 * jj];
#pragma unroll
            for (int i = 0; i < 4; i++)
#pragma unroll
                for (int jj = 0; jj < 8; jj++)
                    acc[i][jj] = fmaf(p[i], vv[jj], acc[i][jj]);
        }
        __syncthreads();
    }

    float inv[4];
#pragma unroll
    for (int i = 0; i < 4; i++) inv[i] = 1.0f / sL[ty * 4 + i];
#pragma unroll
    for (int i = 0; i < 4; i++) {
        size_t row = base + (size_t)(q0 + ty * 4 + i) * Dc;
#pragma unroll
        for (int jj = 0; jj < 8; jj++)
            O[row + tx + 16 * jj] = acc[i][jj] * inv[i];
    }
}

// ---------------------------------------------------------------------------
// Launch
// ---------------------------------------------------------------------------
extern "C" void kernel_launch(void* const* d_in, const int* in_sizes, int n_in,
                              void* d_out, int out_size) {
    const float* x    = (const float*)d_in[0];
    const float* cosp = (const float*)d_in[1];
    const float* sinp = (const float*)d_in[2];
    const float* Wq   = (const float*)d_in[3];
    const float* Wk   = (const float*)d_in[4];
    const float* Wv   = (const float*)d_in[5];
    const float* Wo   = (const float*)d_in[6];
    float* out = (float*)d_out;

    float *Qb, *Kb, *Vb, *Ab, *xr, *wq, *wk, *wv, *wo;
    cudaGetSymbolAddress((void**)&Qb, g_Q);
    cudaGetSymbolAddress((void**)&Kb, g_K);
    cudaGetSymbolAddress((void**)&Vb, g_V);
    cudaGetSymbolAddress((void**)&Ab, g_A);
    cudaGetSymbolAddress((void**)&xr, g_xr);
    cudaGetSymbolAddress((void**)&wq, g_Wq);
    cudaGetSymbolAddress((void**)&wk, g_Wk);
    cudaGetSymbolAddress((void**)&wv, g_Wv);
    cudaGetSymbolAddress((void**)&wo, g_Wo);

    const size_t gsm = (size_t)GEMM_SMEM * sizeof(float);
    cudaFuncSetAttribute(gemm_tf32, cudaFuncAttributeMaxDynamicSharedMemorySize,
                         (int)gsm);

    // tf32-round all GEMM operands (round-to-nearest, unbiased)
    {
        const int nx = Mc * Dc / 4, nw = Dc * Dc / 4;
        round_tf32<<<(nx + 255) / 256, 256>>>(x,  xr, nx);
        round_tf32<<<(nw + 255) / 256, 256>>>(Wq, wq, nw);
        round_tf32<<<(nw + 255) / 256, 256>>>(Wk, wk, nw);
        round_tf32<<<(nw + 255) / 256, 256>>>(Wv, wv, nw);
        round_tf32<<<(nw + 255) / 256, 256>>>(Wo, wo, nw);
    }

    dim3 ggrid(Dc / 128, Mc / 128);   // (16, 32)

    gemm_tf32<<<ggrid, 256, gsm>>>(xr, wq, Qb, Mc, Dc, Dc);
    gemm_tf32<<<ggrid, 256, gsm>>>(xr, wk, Kb, Mc, Dc, Dc);
    gemm_tf32<<<ggrid, 256, gsm>>>(xr, wv, Vb, Mc, Dc, Dc);

    {
        int total = Bc * Sc * Hc * (DHc / 2);
        dim3 rgrid((total + 255) / 256, 2);
        rope_kernel<<<rgrid, 256>>>(Qb, Kb, cosp, sinp);
    }

    {
        size_t smem = (size_t)FL_SMEMF * sizeof(float);
        cudaFuncSetAttribute(flash_kernel,
                             cudaFuncAttributeMaxDynamicSharedMemorySize,
                             (int)smem);
        dim3 fgrid(Sc / 64, Bc * Hc);   // (32, 32)
        flash_kernel<<<fgrid, 256, smem>>>(Qb, Kb, Vb, Ab);
    }

    // round attention output, then O projection
    {
        const int na = Mc * Dc / 4;
        round_tf32<<<(na + 255) / 256, 256>>>(Ab, Ab, na);
    }
    gemm_tf32<<<ggrid, 256, gsm>>>(Ab, wo, out, Mc, Dc, Dc);
}

// round 3
// speedup vs baseline: 4.0236x; 1.6284x over previous
#include <cuda_runtime.h>
#include <math.h>
#include <stdint.h>

// Problem constants
constexpr int Bc  = 2;
constexpr int Sc  = 2048;
constexpr int Dc  = 2048;
constexpr int Hc  = 16;
constexpr int DHc = 128;
constexpr int Mc  = Bc * Sc;   // 4096 rows for projections

// ---------------------------------------------------------------------------
// Scratch (device globals: allocation-free per harness rules)
// ---------------------------------------------------------------------------
__device__ float g_Q [(size_t)Mc * Dc];
__device__ float g_K [(size_t)Mc * Dc];
__device__ float g_V [(size_t)Mc * Dc];
__device__ float g_A [(size_t)Mc * Dc];   // attention output [b,s,h,dh]
__device__ float g_xr[(size_t)Mc * Dc];   // tf32-rounded x
__device__ float g_Wq[(size_t)Dc * Dc];
__device__ float g_Wk[(size_t)Dc * Dc];
__device__ float g_Wv[(size_t)Dc * Dc];
__device__ float g_Wo[(size_t)Dc * Dc];

#define CP_ASYNC16(dst, src) \
    asm volatile("cp.async.cg.shared.global [%0], [%1], 16;\n" :: "r"(dst), "l"(src))

__device__ __forceinline__ float rna_tf32(float x) {
    uint32_t u;
    asm("cvt.rna.tf32.f32 %0, %1;" : "=r"(u) : "f"(x));
    return __uint_as_float(u);
}

#define MMA_TF32(c, a0, a1, a2, a3, b0, b1)                                    \
    asm volatile(                                                              \
        "mma.sync.aligned.m16n8k8.row.col.f32.tf32.tf32.f32 "                  \
        "{%0,%1,%2,%3}, {%4,%5,%6,%7}, {%8,%9}, {%0,%1,%2,%3};\n"              \
        : "+f"((c)[0]), "+f"((c)[1]), "+f"((c)[2]), "+f"((c)[3])               \
        : "r"(a0), "r"(a1), "r"(a2), "r"(a3), "r"(b0), "r"(b1))

// ---------------------------------------------------------------------------
// Elementwise round-to-nearest tf32
// ---------------------------------------------------------------------------
__global__ void round_tf32(const float* __restrict__ in, float* __restrict__ out,
                           int n4) {
    int i = blockIdx.x * blockDim.x + threadIdx.x;
    if (i >= n4) return;
    float4 v = *(const float4*)(in + (size_t)i * 4);
    float4 o;
    o.x = rna_tf32(v.x); o.y = rna_tf32(v.y);
    o.z = rna_tf32(v.z); o.w = rna_tf32(v.w);
    *(float4*)(out + (size_t)i * 4) = o;
}

// ---------------------------------------------------------------------------
// tf32 mma.sync GEMM:  C[M,N] = A[M,K] @ B[N,K]^T  (unchanged from round 2)
// ---------------------------------------------------------------------------
constexpr int GSTRIDE = 36;
constexpr int GEMM_SMEM = 2 * 2 * 128 * GSTRIDE;

__global__ void __launch_bounds__(256) gemm_tf32(const float* __restrict__ A,
                                                 const float* __restrict__ B,
                                                 float* __restrict__ C,
                                                 int M, int N, int K) {
    extern __shared__ float smem[];
    float* sA = smem;
    float* sB = smem + 2 * 128 * GSTRIDE;

    const int tid  = threadIdx.x;
    const int wid  = tid >> 5;
    const int lane = tid & 31;
    const int wm = (wid & 3) * 32;
    const int wn = (wid >> 2) * 64;
    const int gp = lane >> 2;
    const int t4 = lane & 3;
    const int m0 = blockIdx.y * 128;
    const int n0 = blockIdx.x * 128;

    const int lrow = tid >> 3;
    const int lcol = (tid & 7) * 4;
    const float* Ag = A + (size_t)(m0 + lrow) * K + lcol;
    const float* Bg = B + (size_t)(n0 + lrow) * K + lcol;

    const uint32_t sA_u = (uint32_t)__cvta_generic_to_shared(sA);
    const uint32_t sB_u = (uint32_t)__cvta_generic_to_shared(sB);

    float acc[2][8][4];
#pragma unroll
    for (int im = 0; im < 2; im++)
#pragma unroll
        for (int in_ = 0; in_ < 8; in_++)
#pragma unroll
            for (int r = 0; r < 4; r++) acc[im][in_][r] = 0.f;

    const int nt = K / 32;

    {
#pragma unroll
        for (int p = 0; p < 4; p++) {
            uint32_t da = sA_u + (uint32_t)(((lrow + p * 32) * GSTRIDE + lcol) * 4);
            uint32_t db = sB_u + (uint32_t)(((lrow + p * 32) * GSTRIDE + lcol) * 4);
            CP_ASYNC16(da, Ag + (size_t)p * 32 * K);
            CP_ASYNC16(db, Bg + (size_t)p * 32 * K);
        }
        asm volatile("cp.async.commit_group;\n");
    }

    for (int kt = 0; kt < nt; kt++) {
        const int cur = kt & 1;
        if (kt + 1 < nt) {
            const int nb = cur ^ 1;
            const int k0 = (kt + 1) * 32;
#pragma unroll
            for (int p = 0; p < 4; p++) {
                uint32_t da = sA_u + (uint32_t)((((nb * 128) + lrow + p * 32) * GSTRIDE + lcol) * 4);
                uint32_t db = sB_u + (uint32_t)((((nb * 128) + lrow + p * 32) * GSTRIDE + lcol) * 4);
                CP_ASYNC16(da, Ag + (size_t)p * 32 * K + k0);
                CP_ASYNC16(db, Bg + (size_t)p * 32 * K + k0);
            }
            asm volatile("cp.async.commit_group;\n");
            asm volatile("cp.async.wait_group 1;\n");
        } else {
            asm volatile("cp.async.wait_group 0;\n");
        }
        __syncthreads();

        const float* cA = sA + cur * 128 * GSTRIDE;
        const float* cB = sB + cur * 128 * GSTRIDE;

#pragma unroll
        for (int ka = 0; ka < 4; ka++) {
            const int kk = ka * 8;
            uint32_t af[2][4];
#pragma unroll
            for (int im = 0; im < 2; im++) {
                const float* p = cA + (wm + im * 16 + gp) * GSTRIDE + kk + t4;
                af[im][0] = __float_as_uint(p[0]);
                af[im][1] = __float_as_uint(p[8 * GSTRIDE]);
                af[im][2] = __float_as_uint(p[4]);
                af[im][3] = __float_as_uint(p[8 * GSTRIDE + 4]);
            }
            uint32_t bf[8][2];
#pragma unroll
            for (int in_ = 0; in_ < 8; in_++) {
                const float* p = cB + (wn + in_ * 8 + gp) * GSTRIDE + kk + t4;
                bf[in_][0] = __float_as_uint(p[0]);
                bf[in_][1] = __float_as_uint(p[4]);
            }
#pragma unroll
            for (int im = 0; im < 2; im++)
#pragma unroll
                for (int in_ = 0; in_ < 8; in_++)
                    MMA_TF32(acc[im][in_], af[im][0], af[im][1], af[im][2],
                             af[im][3], bf[in_][0], bf[in_][1]);
        }
        __syncthreads();
    }

#pragma unroll
    for (int im = 0; im < 2; im++) {
        const int mA = m0 + wm + im * 16 + gp;
#pragma unroll
        for (int in_ = 0; in_ < 8; in_++) {
            const int n = n0 + wn + in_ * 8 + 2 * t4;
            *(float2*)(C + (size_t)mA * N + n) =
                make_float2(acc[im][in_][0], acc[im][in_][1]);
            *(float2*)(C + (size_t)(mA + 8) * N + n) =
                make_float2(acc[im][in_][2], acc[im][in_][3]);
        }
    }
}

// ---------------------------------------------------------------------------
// RoPE in-place. K output is tf32-rounded (fed raw into mma B-frags).
// Q stays fp32 (flash scales then rounds it).
// ---------------------------------------------------------------------------
__global__ void rope_kernel(float* __restrict__ Q, float* __restrict__ K,
                            const float* __restrict__ cosp,
                            const float* __restrict__ sinp) {
    int i = blockIdx.x * blockDim.x + threadIdx.x;
    const int total = Bc * Sc * Hc * (DHc / 2);
    if (i >= total) return;
    int dh = i & 63;
    int h  = (i >> 6) & (Hc - 1);
    int bs = i >> 10;
    int s  = bs & (Sc - 1);
    size_t base = (size_t)bs * Dc + h * DHc;

    float c  = cosp[s * DHc + dh];
    float sn = sinp[s * DHc + dh];
    float* p = blockIdx.y ? K : Q;
    float x1 = p[base + dh];
    float x2 = p[base + dh + 64];
    float r1 = x1 * c - x2 * sn;
    float r2 = x2 * c + x1 * sn;
    if (blockIdx.y) { r1 = rna_tf32(r1); r2 = rna_tf32(r2); }
    p[base + dh]      = r1;
    p[base + dh + 64] = r2;
}

// ---------------------------------------------------------------------------
// Tensor-core flash attention (tf32 mma, causal).
// 128 threads = 4 warps; BM=64 (16 q rows / warp), BN=64, DH=128.
// smem: sQ[64][132] (scaled, tf32), sKV[64][136] (K uses stride 132,
// V uses stride 136 — both conflict-free for their fragment patterns),
// sP[64][68] (P routed C-layout -> A-layout through smem).
// Softmax stats per-row in registers (quad shfl reductions).
// ---------------------------------------------------------------------------
constexpr int QS = 132;
constexpr int KSK = 132;   // stride during K phase
constexpr int KSV = 136;   // stride during V phase
constexpr int PSS = 68;
constexpr int FL_SMEMF = 64 * QS + 64 * KSV + 64 * PSS;   // 21504 floats = 84KB

__global__ void __launch_bounds__(128) flash_tc(const float* __restrict__ Q,
                                                const float* __restrict__ K,
                                                const float* __restrict__ V,
                                                float* __restrict__ O) {
    extern __shared__ float smem[];
    float* sQ  = smem;
    float* sKV = smem + 64 * QS;
    float* sP  = sKV + 64 * KSV;

    const int tid  = threadIdx.x;
    const int wid  = tid >> 5;
    const int lane = tid & 31;
    const int gp   = lane >> 2;
    const int t4   = lane & 3;
    const int qb   = blockIdx.x;
    const int bh   = blockIdx.y;
    const int b    = bh >> 4;
    const int h    = bh & (Hc - 1);
    const size_t base = ((size_t)b * Sc) * Dc + (size_t)h * DHc;
    const int q0   = qb * 64;
    const int wrow = wid * 16;
    const float scale = 0.08838834764831845f;   // 1/sqrt(128)

    const uint32_t skv_u = (uint32_t)__cvta_generic_to_shared(sKV);

    // Q tile: load, scale, tf32-round
    for (int i = tid; i < 2048; i += 128) {
        int r = i >> 5, c4 = (i & 31) << 2;
        float4 v = *(const float4*)(Q + base + (size_t)(q0 + r) * Dc + c4);
        float* d = sQ + r * QS + c4;
        d[0] = rna_tf32(v.x * scale);
        d[1] = rna_tf32(v.y * scale);
        d[2] = rna_tf32(v.z * scale);
        d[3] = rna_tf32(v.w * scale);
    }

    float o[16][4];
#pragma unroll
    for (int n = 0; n < 16; n++)
#pragma unroll
        for (int r = 0; r < 4; r++) o[n][r] = 0.f;
    float m0 = -1e30f, m1 = -1e30f, l0 = 0.f, l1 = 0.f;

    const int r0loc = wrow + gp;       // this thread's q rows (block-local)
    const int r1loc = r0loc + 8;

    for (int j = 0; j <= qb; ++j) {
        const int k0r = j * 64;

        // ---- K tile -> sKV (stride 132) ----
        for (int i = tid; i < 2048; i += 128) {
            int r = i >> 5, c4 = (i & 31) << 2;
            uint32_t dst = skv_u + (uint32_t)((r * KSK + c4) * 4);
            CP_ASYNC16(dst, K + base + (size_t)(k0r + r) * Dc + c4);
        }
        asm volatile("cp.async.commit_group;\n");
        asm volatile("cp.async.wait_group 0;\n");
        __syncthreads();

        // ---- S = Qs @ K^T ----
        float sacc[8][4];
#pragma unroll
        for (int n = 0; n < 8; n++)
#pragma unroll
            for (int r = 0; r < 4; r++) sacc[n][r] = 0.f;

#pragma unroll 4
        for (int kk = 0; kk < 16; kk++) {
            const int kb = kk * 8;
            const float* qa = sQ + r0loc * QS + kb + t4;
            uint32_t a0 = __float_as_uint(qa[0]);
            uint32_t a1 = __float_as_uint(qa[8 * QS]);
            uint32_t a2 = __float_as_uint(qa[4]);
            uint32_t a3 = __float_as_uint(qa[8 * QS + 4]);
#pragma unroll
            for (int nt = 0; nt < 8; nt++) {
                const float* kb_p = sKV + (nt * 8 + gp) * KSK + kb + t4;
                uint32_t b0 = __float_as_uint(kb_p[0]);
                uint32_t b1 = __float_as_uint(kb_p[4]);
                MMA_TF32(sacc[nt], a0, a1, a2, a3, b0, b1);
            }
        }

        // ---- causal mask on diagonal tile ----
        if (j == qb) {
#pragma unroll
            for (int nt = 0; nt < 8; nt++) {
                int c0 = nt * 8 + 2 * t4;
                if (c0 > r0loc)     sacc[nt][0] = -1e30f;
                if (c0 + 1 > r0loc) sacc[nt][1] = -1e30f;
                if (c0 > r1loc)     sacc[nt][2] = -1e30f;
                if (c0 + 1 > r1loc) sacc[nt][3] = -1e30f;
            }
        }

        // ---- online softmax (register stats, quad reductions) ----
        float mx0 = -1e30f, mx1 = -1e30f;
#pragma unroll
        for (int nt = 0; nt < 8; nt++) {
            mx0 = fmaxf(mx0, fmaxf(sacc[nt][0], sacc[nt][1]));
            mx1 = fmaxf(mx1, fmaxf(sacc[nt][2], sacc[nt][3]));
        }
        mx0 = fmaxf(mx0, __shfl_xor_sync(0xffffffff, mx0, 1));
        mx0 = fmaxf(mx0, __shfl_xor_sync(0xffffffff, mx0, 2));
        mx1 = fmaxf(mx1, __shfl_xor_sync(0xffffffff, mx1, 1));
        mx1 = fmaxf(mx1, __shfl_xor_sync(0xffffffff, mx1, 2));

        float m0n = fmaxf(m0, mx0);
        float m1n = fmaxf(m1, mx1);
        float corr0 = __expf(m0 - m0n);
        float corr1 = __expf(m1 - m1n);
        m0 = m0n; m1 = m1n;

        float ls0 = 0.f, ls1 = 0.f;
#pragma unroll
        for (int nt = 0; nt < 8; nt++) {
            float p0 = __expf(sacc[nt][0] - m0);
            float p1 = __expf(sacc[nt][1] - m0);
            float p2 = __expf(sacc[nt][2] - m1);
            float p3 = __expf(sacc[nt][3] - m1);
            ls0 += p0 + p1;
            ls1 += p2 + p3;
            int c0 = nt * 8 + 2 * t4;
            *(float2*)(sP + r0loc * PSS + c0) =
                make_float2(rna_tf32(p0), rna_tf32(p1));
            *(float2*)(sP + r1loc * PSS + c0) =
                make_float2(rna_tf32(p2), rna_tf32(p3));
        }
        ls0 += __shfl_xor_sync(0xffffffff, ls0, 1);
        ls0 += __shfl_xor_sync(0xffffffff, ls0, 2);
        ls1 += __shfl_xor_sync(0xffffffff, ls1, 1);
        ls1 += __shfl_xor_sync(0xffffffff, ls1, 2);
        l0 = l0 * corr0 + ls0;
        l1 = l1 * corr1 + ls1;
        __syncwarp();

        // rescale O accumulators
#pragma unroll
        for (int nt = 0; nt < 16; nt++) {
            o[nt][0] *= corr0; o[nt][1] *= corr0;
            o[nt][2] *= corr1; o[nt][3] *= corr1;
        }

        __syncthreads();   // all warps done reading K before V overwrites

        // ---- V tile -> sKV (stride 136) ----
        for (int i = tid; i < 2048; i += 128) {
            int r = i >> 5, c4 = (i & 31) << 2;
            uint32_t dst = skv_u + (uint32_t)((r * KSV + c4) * 4);
            CP_ASYNC16(dst, V + base + (size_t)(k0r + r) * Dc + c4);
        }
        asm volatile("cp.async.commit_group;\n");
        asm volatile("cp.async.wait_group 0;\n");
        __syncthreads();

        // ---- O += P @ V ----
#pragma unroll 4
        for (int kk = 0; kk < 8; kk++) {
            const int kb = kk * 8;
            const float* pa = sP + r0loc * PSS + kb + t4;
            uint32_t a0 = __float_as_uint(pa[0]);
            uint32_t a1 = __float_as_uint(pa[8 * PSS]);
            uint32_t a2 = __float_as_uint(pa[4]);
            uint32_t a3 = __float_as_uint(pa[8 * PSS + 4]);
#pragma unroll
            for (int nt = 0; nt < 16; nt++) {
                const float* vp = sKV + (kb + t4) * KSV + nt * 8 + gp;
                uint32_t b0 = __float_as_uint(vp[0]);
                uint32_t b1 = __float_as_uint(vp[4 * KSV]);
                MMA_TF32(o[nt], a0, a1, a2, a3, b0, b1);
            }
        }
        __syncthreads();   // before next K load overwrites sKV
    }

    // ---- epilogue ----
    float inv0 = 1.0f / l0, inv1 = 1.0f / l1;
    const size_t row0 = base + (size_t)(q0 + r0loc) * Dc;
    const size_t row1 = base + (size_t)(q0 + r1loc) * Dc;
#pragma unroll
    for (int nt = 0; nt < 16; nt++) {
        int c0 = nt * 8 + 2 * t4;
        *(float2*)(O + row0 + c0) = make_float2(o[nt][0] * inv0, o[nt][1] * inv0);
        *(float2*)(O + row1 + c0) = make_float2(o[nt][2] * inv1, o[nt][3] * inv1);
    }
}

// ---------------------------------------------------------------------------
// Launch
// ---------------------------------------------------------------------------
extern "C" void kernel_launch(void* const* d_in, const int* in_sizes, int n_in,
                              void* d_out, int out_size) {
    const float* x    = (const float*)d_in[0];
    const float* cosp = (const float*)d_in[1];
    const float* sinp = (const float*)d_in[2];
    const float* Wq   = (const float*)d_in[3];
    const float* Wk   = (const float*)d_in[4];
    const float* Wv   = (const float*)d_in[5];
    const float* Wo   = (const float*)d_in[6];
    float* out = (float*)d_out;

    float *Qb, *Kb, *Vb, *Ab, *xr, *wq, *wk, *wv, *wo;
    cudaGetSymbolAddress((void**)&Qb, g_Q);
    cudaGetSymbolAddress((void**)&Kb, g_K);
    cudaGetSymbolAddress((void**)&Vb, g_V);
    cudaGetSymbolAddress((void**)&Ab, g_A);
    cudaGetSymbolAddress((void**)&xr, g_xr);
    cudaGetSymbolAddress((void**)&wq, g_Wq);
    cudaGetSymbolAddress((void**)&wk, g_Wk);
    cudaGetSymbolAddress((void**)&wv, g_Wv);
    cudaGetSymbolAddress((void**)&wo, g_Wo);

    const size_t gsm = (size_t)GEMM_SMEM * sizeof(float);
    cudaFuncSetAttribute(gemm_tf32, cudaFuncAttributeMaxDynamicSharedMemorySize,
                         (int)gsm);

    // tf32-round all GEMM operands
    {
        const int nx = Mc * Dc / 4, nw = Dc * Dc / 4;
        round_tf32<<<(nx + 255) / 256, 256>>>(x,  xr, nx);
        round_tf32<<<(nw + 255) / 256, 256>>>(Wq, wq, nw);
        round_tf32<<<(nw + 255) / 256, 256>>>(Wk, wk, nw);
        round_tf32<<<(nw + 255) / 256, 256>>>(Wv, wv, nw);
        round_tf32<<<(nw + 255) / 256, 256>>>(Wo, wo, nw);
    }

    dim3 ggrid(Dc / 128, Mc / 128);   // (16, 32)

    gemm_tf32<<<ggrid, 256, gsm>>>(xr, wq, Qb, Mc, Dc, Dc);
    gemm_tf32<<<ggrid, 256, gsm>>>(xr, wk, Kb, Mc, Dc, Dc);
    gemm_tf32<<<ggrid, 256, gsm>>>(xr, wv, Vb, Mc, Dc, Dc);

    // RoPE (rounds K to tf32); round V to tf32 for the PV mma
    {
        int total = Bc * Sc * Hc * (DHc / 2);
        dim3 rgrid((total + 255) / 256, 2);
        rope_kernel<<<rgrid, 256>>>(Qb, Kb, cosp, sinp);
        const int nv = Mc * Dc / 4;
        round_tf32<<<(nv + 255) / 256, 256>>>(Vb, Vb, nv);
    }

    // Tensor-core flash attention
    {
        size_t smem = (size_t)FL_SMEMF * sizeof(float);
        cudaFuncSetAttribute(flash_tc,
                             cudaFuncAttributeMaxDynamicSharedMemorySize,
                             (int)smem);
        dim3 fgrid(Sc / 64, Bc * Hc);   // (32, 32)
        flash_tc<<<fgrid, 128, smem>>>(Qb, Kb, Vb, Ab);
    }

    // round attention output, then O projection
    {
        const int na = Mc * Dc / 4;
        round_tf32<<<(na + 255) / 256, 256>>>(Ab, Ab, na);
    }
    gemm_tf32<<<ggrid, 256, gsm>>>(Ab, wo, out, Mc, Dc, Dc);
}

// round 4
// speedup vs baseline: 4.0564x; 1.0082x over previous
#include <cuda_runtime.h>
#include <math.h>
#include <stdint.h>

// Problem constants
constexpr int Bc  = 2;
constexpr int Sc  = 2048;
constexpr int Dc  = 2048;
constexpr int Hc  = 16;
constexpr int DHc = 128;
constexpr int Mc  = Bc * Sc;   // 4096 rows for projections

// ---------------------------------------------------------------------------
// Scratch (device globals: allocation-free per harness rules)
// ---------------------------------------------------------------------------
__device__ float g_Q [(size_t)Mc * Dc];
__device__ float g_K [(size_t)Mc * Dc];
__device__ float g_V [(size_t)Mc * Dc];
__device__ float g_A [(size_t)Mc * Dc];   // attention output [b,s,h,dh]
__device__ float g_xr[(size_t)Mc * Dc];   // tf32-rounded x
__device__ float g_Wq[(size_t)Dc * Dc];
__device__ float g_Wk[(size_t)Dc * Dc];
__device__ float g_Wv[(size_t)Dc * Dc];
__device__ float g_Wo[(size_t)Dc * Dc];

#define CP_ASYNC16(dst, src) \
    asm volatile("cp.async.cg.shared.global [%0], [%1], 16;\n" :: "r"(dst), "l"(src))

__device__ __forceinline__ float rna_tf32(float x) {
    uint32_t u;
    asm("cvt.rna.tf32.f32 %0, %1;" : "=r"(u) : "f"(x));
    return __uint_as_float(u);
}

#define MMA_TF32(c, a0, a1, a2, a3, b0, b1)                                    \
    asm volatile(                                                              \
        "mma.sync.aligned.m16n8k8.row.col.f32.tf32.tf32.f32 "                  \
        "{%0,%1,%2,%3}, {%4,%5,%6,%7}, {%8,%9}, {%0,%1,%2,%3};\n"              \
        : "+f"((c)[0]), "+f"((c)[1]), "+f"((c)[2]), "+f"((c)[3])               \
        : "r"(a0), "r"(a1), "r"(a2), "r"(a3), "r"(b0), "r"(b1))

// ---------------------------------------------------------------------------
// Elementwise round-to-nearest tf32 (inputs only; V/A rounds are fused)
// ---------------------------------------------------------------------------
__global__ void round_tf32(const float* __restrict__ in, float* __restrict__ out,
                           int n4) {
    int i = blockIdx.x * blockDim.x + threadIdx.x;
    if (i >= n4) return;
    float4 v = *(const float4*)(in + (size_t)i * 4);
    float4 o;
    o.x = rna_tf32(v.x); o.y = rna_tf32(v.y);
    o.z = rna_tf32(v.z); o.w = rna_tf32(v.w);
    *(float4*)(out + (size_t)i * 4) = o;
}

// ---------------------------------------------------------------------------
// tf32 mma.sync GEMM:  C[M,N] = A[M,K] @ B[N,K]^T   (row-major, K contiguous)
// BM=BN=128, BK=32, 128 thr = 4 warps (2m x 2n), warp tile 64x64,
// m16n8k8 atoms, cp.async double-buffered, smem stride 36 (conflict-free).
// MMA:LDS issue ratio 1:1 (vs 0.67 in the 32x64-warp-tile version).
// roundC != 0 rounds the fp32 result to tf32 in the epilogue.
// ---------------------------------------------------------------------------
constexpr int GSTRIDE = 36;
constexpr int GEMM_SMEM = 2 * 2 * 128 * GSTRIDE;   // floats = 73.7KB

__global__ void __launch_bounds__(128) gemm_tf32(const float* __restrict__ A,
                                                 const float* __restrict__ B,
                                                 float* __restrict__ C,
                                                 int M, int N, int K,
                                                 int roundC) {
    extern __shared__ float smem[];
    float* sA = smem;                      // [2][128][36]
    float* sB = smem + 2 * 128 * GSTRIDE;  // [2][128][36]

    const int tid  = threadIdx.x;
    const int wid  = tid >> 5;
    const int lane = tid & 31;
    const int wm = (wid & 1) * 64;     // warp m offset
    const int wn = (wid >> 1) * 64;    // warp n offset
    const int gp = lane >> 2;
    const int t4 = lane & 3;
    const int m0 = blockIdx.y * 128;
    const int n0 = blockIdx.x * 128;

    // global->smem: 128 threads, 16 rows x 8 float4 per pass, 8 passes each
    const int lrow = tid >> 3;         // 0..15
    const int lcol = (tid & 7) * 4;    // 0..28
    const float* Ag = A + (size_t)(m0 + lrow) * K + lcol;
    const float* Bg = B + (size_t)(n0 + lrow) * K + lcol;

    const uint32_t sA_u = (uint32_t)__cvta_generic_to_shared(sA);
    const uint32_t sB_u = (uint32_t)__cvta_generic_to_shared(sB);

    float acc[4][8][4];
#pragma unroll
    for (int im = 0; im < 4; im++)
#pragma unroll
        for (int in_ = 0; in_ < 8; in_++)
#pragma unroll
            for (int r = 0; r < 4; r++) acc[im][in_][r] = 0.f;

    const int nt = K / 32;

    {
#pragma unroll
        for (int p = 0; p < 8; p++) {
            uint32_t da = sA_u + (uint32_t)(((lrow + p * 16) * GSTRIDE + lcol) * 4);
            uint32_t db = sB_u + (uint32_t)(((lrow + p * 16) * GSTRIDE + lcol) * 4);
            CP_ASYNC16(da, Ag + (size_t)p * 16 * K);
            CP_ASYNC16(db, Bg + (size_t)p * 16 * K);
        }
        asm volatile("cp.async.commit_group;\n");
    }

    for (int kt = 0; kt < nt; kt++) {
        const int cur = kt & 1;
        if (kt + 1 < nt) {
            const int nb = cur ^ 1;
            const int k0 = (kt + 1) * 32;
#pragma unroll
            for (int p = 0; p < 8; p++) {
                uint32_t da = sA_u + (uint32_t)((((nb * 128) + lrow + p * 16) * GSTRIDE + lcol) * 4);
                uint32_t db = sB_u + (uint32_t)((((nb * 128) + lrow + p * 16) * GSTRIDE + lcol) * 4);
                CP_ASYNC16(da, Ag + (size_t)p * 16 * K + k0);
                CP_ASYNC16(db, Bg + (size_t)p * 16 * K + k0);
            }
            asm volatile("cp.async.commit_group;\n");
            asm volatile("cp.async.wait_group 1;\n");
        } else {
            asm volatile("cp.async.wait_group 0;\n");
        }
        __syncthreads();

        const float* cA = sA + cur * 128 * GSTRIDE;
        const float* cB = sB + cur * 128 * GSTRIDE;

#pragma unroll
        for (int ka = 0; ka < 4; ka++) {
            const int kk = ka * 8;
            uint32_t af[4][4];
#pragma unroll
            for (int im = 0; im < 4; im++) {
                const float* p = cA + (wm + im * 16 + gp) * GSTRIDE + kk + t4;
                af[im][0] = __float_as_uint(p[0]);
                af[im][1] = __float_as_uint(p[8 * GSTRIDE]);
                af[im][2] = __float_as_uint(p[4]);
                af[im][3] = __float_as_uint(p[8 * GSTRIDE + 4]);
            }
            uint32_t bf[8][2];
#pragma unroll
            for (int in_ = 0; in_ < 8; in_++) {
                const float* p = cB + (wn + in_ * 8 + gp) * GSTRIDE + kk + t4;
                bf[in_][0] = __float_as_uint(p[0]);
                bf[in_][1] = __float_as_uint(p[4]);
            }
#pragma unroll
            for (int im = 0; im < 4; im++)
#pragma unroll
                for (int in_ = 0; in_ < 8; in_++)
                    MMA_TF32(acc[im][in_], af[im][0], af[im][1], af[im][2],
                             af[im][3], bf[in_][0], bf[in_][1]);
        }
        __syncthreads();
    }

    // epilogue (optionally tf32-round the result)
    if (roundC) {
#pragma unroll
        for (int im = 0; im < 4; im++)
#pragma unroll
            for (int in_ = 0; in_ < 8; in_++)
#pragma unroll
                for (int r = 0; r < 4; r++)
                    acc[im][in_][r] = rna_tf32(acc[im][in_][r]);
    }
#pragma unroll
    for (int im = 0; im < 4; im++) {
        const int mA = m0 + wm + im * 16 + gp;
#pragma unroll
        for (int in_ = 0; in_ < 8; in_++) {
            const int n = n0 + wn + in_ * 8 + 2 * t4;
            *(float2*)(C + (size_t)mA * N + n) =
                make_float2(acc[im][in_][0], acc[im][in_][1]);
            *(float2*)(C + (size_t)(mA + 8) * N + n) =
                make_float2(acc[im][in_][2], acc[im][in_][3]);
        }
    }
}

// ---------------------------------------------------------------------------
// RoPE in-place. K output is tf32-rounded (fed raw into mma B-frags).
// ---------------------------------------------------------------------------
__global__ void rope_kernel(float* __restrict__ Q, float* __restrict__ K,
                            const float* __restrict__ cosp,
                            const float* __restrict__ sinp) {
    int i = blockIdx.x * blockDim.x + threadIdx.x;
    const int total = Bc * Sc * Hc * (DHc / 2);
    if (i >= total) return;
    int dh = i & 63;
    int h  = (i >> 6) & (Hc - 1);
    int bs = i >> 10;
    int s  = bs & (Sc - 1);
    size_t base = (size_t)bs * Dc + h * DHc;

    float c  = cosp[s * DHc + dh];
    float sn = sinp[s * DHc + dh];
    float* p = blockIdx.y ? K : Q;
    float x1 = p[base + dh];
    float x2 = p[base + dh + 64];
    float r1 = x1 * c - x2 * sn;
    float r2 = x2 * c + x1 * sn;
    if (blockIdx.y) { r1 = rna_tf32(r1); r2 = rna_tf32(r2); }
    p[base + dh]      = r1;
    p[base + dh + 64] = r2;
}

// ---------------------------------------------------------------------------
// Tensor-core flash attention (tf32 mma, causal). Unchanged structure from
// round 3, plus fused tf32 rounding of the output (feeds the O projection).
// ---------------------------------------------------------------------------
constexpr int QS = 132;
constexpr int KSK = 132;
constexpr int KSV = 136;
constexpr int PSS = 68;
constexpr int FL_SMEMF = 64 * QS + 64 * KSV + 64 * PSS;   // 84KB

__global__ void __launch_bounds__(128) flash_tc(const float* __restrict__ Q,
                                                const float* __restrict__ K,
                                                const float* __restrict__ V,
                                                float* __restrict__ O) {
    extern __shared__ float smem[];
    float* sQ  = smem;
    float* sKV = smem + 64 * QS;
    float* sP  = sKV + 64 * KSV;

    const int tid  = threadIdx.x;
    const int wid  = tid >> 5;
    const int lane = tid & 31;
    const int gp   = lane >> 2;
    const int t4   = lane & 3;
    const int qb   = blockIdx.x;
    const int bh   = blockIdx.y;
    const int b    = bh >> 4;
    const int h    = bh & (Hc - 1);
    const size_t base = ((size_t)b * Sc) * Dc + (size_t)h * DHc;
    const int q0   = qb * 64;
    const int wrow = wid * 16;
    const float scale = 0.08838834764831845f;   // 1/sqrt(128)

    const uint32_t skv_u = (uint32_t)__cvta_generic_to_shared(sKV);

    for (int i = tid; i < 2048; i += 128) {
        int r = i >> 5, c4 = (i & 31) << 2;
        float4 v = *(const float4*)(Q + base + (size_t)(q0 + r) * Dc + c4);
        float* d = sQ + r * QS + c4;
        d[0] = rna_tf32(v.x * scale);
        d[1] = rna_tf32(v.y * scale);
        d[2] = rna_tf32(v.z * scale);
        d[3] = rna_tf32(v.w * scale);
    }

    float o[16][4];
#pragma unroll
    for (int n = 0; n < 16; n++)
#pragma unroll
        for (int r = 0; r < 4; r++) o[n][r] = 0.f;
    float m0 = -1e30f, m1 = -1e30f, l0 = 0.f, l1 = 0.f;

    const int r0loc = wrow + gp;
    const int r1loc = r0loc + 8;

    for (int j = 0; j <= qb; ++j) {
        const int k0r = j * 64;

        for (int i = tid; i < 2048; i += 128) {
            int r = i >> 5, c4 = (i & 31) << 2;
            uint32_t dst = skv_u + (uint32_t)((r * KSK + c4) * 4);
            CP_ASYNC16(dst, K + base + (size_t)(k0r + r) * Dc + c4);
        }
        asm volatile("cp.async.commit_group;\n");
        asm volatile("cp.async.wait_group 0;\n");
        __syncthreads();

        float sacc[8][4];
#pragma unroll
        for (int n = 0; n < 8; n++)
#pragma unroll
            for (int r = 0; r < 4; r++) sacc[n][r] = 0.f;

#pragma unroll 4
        for (int kk = 0; kk < 16; kk++) {
            const int kb = kk * 8;
            const float* qa = sQ + r0loc * QS + kb + t4;
            uint32_t a0 = __float_as_uint(qa[0]);
            uint32_t a1 = __float_as_uint(qa[8 * QS]);
            uint32_t a2 = __float_as_uint(qa[4]);
            uint32_t a3 = __float_as_uint(qa[8 * QS + 4]);
#pragma unroll
            for (int nt = 0; nt < 8; nt++) {
                const float* kb_p = sKV + (nt * 8 + gp) * KSK + kb + t4;
                uint32_t b0 = __float_as_uint(kb_p[0]);
                uint32_t b1 = __float_as_uint(kb_p[4]);
                MMA_TF32(sacc[nt], a0, a1, a2, a3, b0, b1);
            }
        }

        if (j == qb) {
#pragma unroll
            for (int nt = 0; nt < 8; nt++) {
                int c0 = nt * 8 + 2 * t4;
                if (c0 > r0loc)     sacc[nt][0] = -1e30f;
                if (c0 + 1 > r0loc) sacc[nt][1] = -1e30f;
                if (c0 > r1loc)     sacc[nt][2] = -1e30f;
                if (c0 + 1 > r1loc) sacc[nt][3] = -1e30f;
            }
        }

        float mx0 = -1e30f, mx1 = -1e30f;
#pragma unroll
        for (int nt = 0; nt < 8; nt++) {
            mx0 = fmaxf(mx0, fmaxf(sacc[nt][0], sacc[nt][1]));
            mx1 = fmaxf(mx1, fmaxf(sacc[nt][2], sacc[nt][3]));
        }
        mx0 = fmaxf(mx0, __shfl_xor_sync(0xffffffff, mx0, 1));
        mx0 = fmaxf(mx0, __shfl_xor_sync(0xffffffff, mx0, 2));
        mx1 = fmaxf(mx1, __shfl_xor_sync(0xffffffff, mx1, 1));
        mx1 = fmaxf(mx1, __shfl_xor_sync(0xffffffff, mx1, 2));

        float m0n = fmaxf(m0, mx0);
        float m1n = fmaxf(m1, mx1);
        float corr0 = __expf(m0 - m0n);
        float corr1 = __expf(m1 - m1n);
        m0 = m0n; m1 = m1n;

        float ls0 = 0.f, ls1 = 0.f;
#pragma unroll
        for (int nt = 0; nt < 8; nt++) {
            float p0 = __expf(sacc[nt][0] - m0);
            float p1 = __expf(sacc[nt][1] - m0);
            float p2 = __expf(sacc[nt][2] - m1);
            float p3 = __expf(sacc[nt][3] - m1);
            ls0 += p0 + p1;
            ls1 += p2 + p3;
            int c0 = nt * 8 + 2 * t4;
            *(float2*)(sP + r0loc * PSS + c0) =
                make_float2(rna_tf32(p0), rna_tf32(p1));
            *(float2*)(sP + r1loc * PSS + c0) =
                make_float2(rna_tf32(p2), rna_tf32(p3));
        }
        ls0 += __shfl_xor_sync(0xffffffff, ls0, 1);
        ls0 += __shfl_xor_sync(0xffffffff, ls0, 2);
        ls1 += __shfl_xor_sync(0xffffffff, ls1, 1);
        ls1 += __shfl_xor_sync(0xffffffff, ls1, 2);
        l0 = l0 * corr0 + ls0;
        l1 = l1 * corr1 + ls1;
        __syncwarp();

#pragma unroll
        for (int nt = 0; nt < 16; nt++) {
            o[nt][0] *= corr0; o[nt][1] *= corr0;
            o[nt][2] *= corr1; o[nt][3] *= corr1;
        }

        __syncthreads();

        for (int i = tid; i < 2048; i += 128) {
            int r = i >> 5, c4 = (i & 31) << 2;
            uint32_t dst = skv_u + (uint32_t)((r * KSV + c4) * 4);
            CP_ASYNC16(dst, V + base + (size_t)(k0r + r) * Dc + c4);
        }
        asm volatile("cp.async.commit_group;\n");
        asm volatile("cp.async.wait_group 0;\n");
        __syncthreads();

#pragma unroll 4
        for (int kk = 0; kk < 8; kk++) {
            const int kb = kk * 8;
            const float* pa = sP + r0loc * PSS + kb + t4;
            uint32_t a0 = __float_as_uint(pa[0]);
            uint32_t a1 = __float_as_uint(pa[8 * PSS]);
            uint32_t a2 = __float_as_uint(pa[4]);
            uint32_t a3 = __float_as_uint(pa[8 * PSS + 4]);
#pragma unroll
            for (int nt = 0; nt < 16; nt++) {
                const float* vp = sKV + (kb + t4) * KSV + nt * 8 + gp;
                uint32_t b0 = __float_as_uint(vp[0]);
                uint32_t b1 = __float_as_uint(vp[4 * KSV]);
                MMA_TF32(o[nt], a0, a1, a2, a3, b0, b1);
            }
        }
        __syncthreads();
    }

    // epilogue: normalize + tf32-round (output feeds the O-projection GEMM)
    float inv0 = 1.0f / l0, inv1 = 1.0f / l1;
    const size_t row0 = base + (size_t)(q0 + r0loc) * Dc;
    const size_t row1 = base + (size_t)(q0 + r1loc) * Dc;
#pragma unroll
    for (int nt = 0; nt < 16; nt++) {
        int c0 = nt * 8 + 2 * t4;
        *(float2*)(O + row0 + c0) =
            make_float2(rna_tf32(o[nt][0] * inv0), rna_tf32(o[nt][1] * inv0));
        *(float2*)(O + row1 + c0) =
            make_float2(rna_tf32(o[nt][2] * inv1), rna_tf32(o[nt][3] * inv1));
    }
}

// ---------------------------------------------------------------------------
// Launch
// ---------------------------------------------------------------------------
extern "C" void kernel_launch(void* const* d_in, const int* in_sizes, int n_in,
                              void* d_out, int out_size) {
    const float* x    = (const float*)d_in[0];
    const float* cosp = (const float*)d_in[1];
    const float* sinp = (const float*)d_in[2];
    const float* Wq   = (const float*)d_in[3];
    const float* Wk   = (const float*)d_in[4];
    const float* Wv   = (const float*)d_in[5];
    const float* Wo   = (const float*)d_in[6];
    float* out = (float*)d_out;

    float *Qb, *Kb, *Vb, *Ab, *xr, *wq, *wk, *wv, *wo;
    cudaGetSymbolAddress((void**)&Qb, g_Q);
    cudaGetSymbolAddress((void**)&Kb, g_K);
    cudaGetSymbolAddress((void**)&Vb, g_V);
    cudaGetSymbolAddress((void**)&Ab, g_A);
    cudaGetSymbolAddress((void**)&xr, g_xr);
    cudaGetSymbolAddress((void**)&wq, g_Wq);
    cudaGetSymbolAddress((void**)&wk, g_Wk);
    cudaGetSymbolAddress((void**)&wv, g_Wv);
    cudaGetSymbolAddress((void**)&wo, g_Wo);

    const size_t gsm = (size_t)GEMM_SMEM * sizeof(float);
    cudaFuncSetAttribute(gemm_tf32, cudaFuncAttributeMaxDynamicSharedMemorySize,
                         (int)gsm);

    // tf32-round GEMM inputs
    {
        const int nx = Mc * Dc / 4, nw = Dc * Dc / 4;
        round_tf32<<<(nx + 255) / 256, 256>>>(x,  xr, nx);
        round_tf32<<<(nw + 255) / 256, 256>>>(Wq, wq, nw);
        round_tf32<<<(nw + 255) / 256, 256>>>(Wk, wk, nw);
        round_tf32<<<(nw + 255) / 256, 256>>>(Wv, wv, nw);
        round_tf32<<<(nw + 255) / 256, 256>>>(Wo, wo, nw);
    }

    dim3 ggrid(Dc / 128, Mc / 128);   // (16, 32)

    gemm_tf32<<<ggrid, 128, gsm>>>(xr, wq, Qb, Mc, Dc, Dc, 0);
    gemm_tf32<<<ggrid, 128, gsm>>>(xr, wk, Kb, Mc, Dc, Dc, 0);
    gemm_tf32<<<ggrid, 128, gsm>>>(xr, wv, Vb, Mc, Dc, Dc, 1);   // round V

    // RoPE (rounds K to tf32)
    {
        int total = Bc * Sc * Hc * (DHc / 2);
        dim3 rgrid((total + 255) / 256, 2);
        rope_kernel<<<rgrid, 256>>>(Qb, Kb, cosp, sinp);
    }

    // Tensor-core flash attention (rounds its output)
    {
        size_t smem = (size_t)FL_SMEMF * sizeof(float);
        cudaFuncSetAttribute(flash_tc,
                             cudaFuncAttributeMaxDynamicSharedMemorySize,
                             (int)smem);
        dim3 fgrid(Sc / 64, Bc * Hc);   // (32, 32)
        flash_tc<<<fgrid, 128, smem>>>(Qb, Kb, Vb, Ab);
    }

    // O projection
    gemm_tf32<<<ggrid, 128, gsm>>>(Ab, wo, out, Mc, Dc, Dc, 0);
}

// round 6
// speedup vs baseline: 6.6853x; 1.6481x over previous
#include <cuda_runtime.h>
#include <cuda_fp16.h>
#include <math.h>
#include <stdint.h>

// Problem constants
constexpr int Bc  = 2;
constexpr int Sc  = 2048;
constexpr int Dc  = 2048;
constexpr int Hc  = 16;
constexpr int DHc = 128;
constexpr int Mc  = Bc * Sc;   // 4096 rows for projections

// ---------------------------------------------------------------------------
// Scratch (device globals: allocation-free per harness rules)
// ---------------------------------------------------------------------------
__device__ float  g_Q [(size_t)Mc * Dc];
__device__ float  g_K [(size_t)Mc * Dc];
__device__ float  g_V [(size_t)Mc * Dc];       // tf32-rounded, for PV mma
__device__ __half g_xh [(size_t)Mc * Dc];
__device__ __half g_Qh [(size_t)Mc * Dc];      // roped + softmax-scaled
__device__ __half g_Kh [(size_t)Mc * Dc];      // roped
__device__ __half g_Ah [(size_t)Mc * Dc];      // attention out (half)
__device__ __half g_wqh[(size_t)Dc * Dc];
__device__ __half g_wkh[(size_t)Dc * Dc];
__device__ __half g_wvh[(size_t)Dc * Dc];
__device__ __half g_woh[(size_t)Dc * Dc];

#define CP_ASYNC16(dst, src) \
    asm volatile("cp.async.cg.shared.global [%0], [%1], 16;\n" :: "r"(dst), "l"(src))

__device__ __forceinline__ float rna_tf32(float x) {
    uint32_t u;
    asm("cvt.rna.tf32.f32 %0, %1;" : "=r"(u) : "f"(x));
    return __uint_as_float(u);
}
__device__ __forceinline__ uint32_t ld32h(const __half* p) {
    return *(const uint32_t*)p;
}

#define MMA_TF32(c, a0, a1, a2, a3, b0, b1)                                    \
    asm volatile(                                                              \
        "mma.sync.aligned.m16n8k8.row.col.f32.tf32.tf32.f32 "                  \
        "{%0,%1,%2,%3}, {%4,%5,%6,%7}, {%8,%9}, {%0,%1,%2,%3};\n"              \
        : "+f"((c)[0]), "+f"((c)[1]), "+f"((c)[2]), "+f"((c)[3])               \
        : "r"(a0), "r"(a1), "r"(a2), "r"(a3), "r"(b0), "r"(b1))

#define MMA_F16(c, a0, a1, a2, a3, b0, b1)                                     \
    asm volatile(                                                              \
        "mma.sync.aligned.m16n8k16.row.col.f32.f16.f16.f32 "                   \
        "{%0,%1,%2,%3}, {%4,%5,%6,%7}, {%8,%9}, {%0,%1,%2,%3};\n"              \
        : "+f"((c)[0]), "+f"((c)[1]), "+f"((c)[2]), "+f"((c)[3])               \
        : "r"(a0), "r"(a1), "r"(a2), "r"(a3), "r"(b0), "r"(b1))

// ---------------------------------------------------------------------------
// fp32 -> fp16 conversion (round-to-nearest)
// ---------------------------------------------------------------------------
__global__ void cvt_half(const float* __restrict__ in, __half* __restrict__ out,
                         int n4) {
    int i = blockIdx.x * blockDim.x + threadIdx.x;
    if (i >= n4) return;
    float4 v = *(const float4*)(in + (size_t)i * 4);
    __half2 h01 = __floats2half2_rn(v.x, v.y);
    __half2 h23 = __floats2half2_rn(v.z, v.w);
    uint2 u;
    u.x = *(uint32_t*)&h01;
    u.y = *(uint32_t*)&h23;
    *(uint2*)(out + (size_t)i * 4) = u;
}

// ---------------------------------------------------------------------------
// fp16 mma GEMM:  C[M,N] = A[M,K] @ B[N,K]^T   (row-major, K contiguous)
// BM=BN=128, BK=32 halves, 128 thr = 4 warps (2m x 2n), warp tile 64x64,
// m16n8k16 atoms, cp.async double-buffered, smem stride 40 halves
// (conflict-free: bank = 4*gp + t4). roundC: tf32-round fp32 result.
// ---------------------------------------------------------------------------
constexpr int HST = 40;                               // halves per smem row
constexpr int GEMM_SMEM_B = 2 * 2 * 128 * HST * 2;    // 40960 bytes

__global__ void __launch_bounds__(128) gemm_f16(const __half* __restrict__ A,
                                                const __half* __restrict__ B,
                                                float* __restrict__ C,
                                                int M, int N, int K,
                                                int roundC) {
    extern __shared__ __half hsm[];
    __half* sA = hsm;                      // [2][128][40]
    __half* sB = hsm + 2 * 128 * HST;      // [2][128][40]

    const int tid  = threadIdx.x;
    const int wid  = tid >> 5;
    const int lane = tid & 31;
    const int wm = (wid & 1) * 64;
    const int wn = (wid >> 1) * 64;
    const int gp = lane >> 2;
    const int t4 = lane & 3;
    const int m0 = blockIdx.y * 128;
    const int n0 = blockIdx.x * 128;

    // loader: 128 rows x 4 segs (8 halves = 16B) per matrix; 4 passes/thread
    const int lrow = tid >> 2;         // 0..31
    const int lseg = tid & 3;          // 0..3
    const __half* Ag = A + (size_t)(m0 + lrow) * K + lseg * 8;
    const __half* Bg = B + (size_t)(n0 + lrow) * K + lseg * 8;

    const uint32_t sA_u = (uint32_t)__cvta_generic_to_shared(sA);
    const uint32_t sB_u = (uint32_t)__cvta_generic_to_shared(sB);

    float acc[4][8][4];
#pragma unroll
    for (int im = 0; im < 4; im++)
#pragma unroll
        for (int in_ = 0; in_ < 8; in_++)
#pragma unroll
            for (int r = 0; r < 4; r++) acc[im][in_][r] = 0.f;

    const int nt = K / 32;

    // prefetch tile 0
    {
#pragma unroll
        for (int p = 0; p < 4; p++) {
            int row = lrow + p * 32;
            uint32_t da = sA_u + (uint32_t)((row * HST + lseg * 8) * 2);
            uint32_t db = sB_u + (uint32_t)((row * HST + lseg * 8) * 2);
            CP_ASYNC16(da, Ag + (size_t)p * 32 * K);
            CP_ASYNC16(db, Bg + (size_t)p * 32 * K);
        }
        asm volatile("cp.async.commit_group;\n");
    }

    for (int kt = 0; kt < nt; kt++) {
        const int cur = kt & 1;
        if (kt + 1 < nt) {
            const int nb = cur ^ 1;
            const int k0 = (kt + 1) * 32;
#pragma unroll
            for (int p = 0; p < 4; p++) {
                int row = lrow + p * 32;
                uint32_t da = sA_u + (uint32_t)((((nb * 128) + row) * HST + lseg * 8) * 2);
                uint32_t db = sB_u + (uint32_t)((((nb * 128) + row) * HST + lseg * 8) * 2);
                CP_ASYNC16(da, Ag + (size_t)p * 32 * K + k0);
                CP_ASYNC16(db, Bg + (size_t)p * 32 * K + k0);
            }
            asm volatile("cp.async.commit_group;\n");
            asm volatile("cp.async.wait_group 1;\n");
        } else {
            asm volatile("cp.async.wait_group 0;\n");
        }
        __syncthreads();

        const __half* cA = sA + cur * 128 * HST;
        const __half* cB = sB + cur * 128 * HST;

#pragma unroll
        for (int ks = 0; ks < 2; ks++) {
            const int kk = ks * 16;
            uint32_t af[4][4];
#pragma unroll
            for (int im = 0; im < 4; im++) {
                const __half* p = cA + (wm + im * 16 + gp) * HST + kk + 2 * t4;
                af[im][0] = ld32h(p);
                af[im][1] = ld32h(p + 8 * HST);
                af[im][2] = ld32h(p + 8);
                af[im][3] = ld32h(p + 8 * HST + 8);
            }
            uint32_t bf[8][2];
#pragma unroll
            for (int in_ = 0; in_ < 8; in_++) {
                const __half* p = cB + (wn + in_ * 8 + gp) * HST + kk + 2 * t4;
                bf[in_][0] = ld32h(p);
                bf[in_][1] = ld32h(p + 8);
            }
#pragma unroll
            for (int im = 0; im < 4; im++)
#pragma unroll
                for (int in_ = 0; in_ < 8; in_++)
                    MMA_F16(acc[im][in_], af[im][0], af[im][1], af[im][2],
                            af[im][3], bf[in_][0], bf[in_][1]);
        }
        __syncthreads();
    }

    if (roundC) {
#pragma unroll
        for (int im = 0; im < 4; im++)
#pragma unroll
            for (int in_ = 0; in_ < 8; in_++)
#pragma unroll
                for (int r = 0; r < 4; r++)
                    acc[im][in_][r] = rna_tf32(acc[im][in_][r]);
    }
#pragma unroll
    for (int im = 0; im < 4; im++) {
        const int mA = m0 + wm + im * 16 + gp;
#pragma unroll
        for (int in_ = 0; in_ < 8; in_++) {
            const int n = n0 + wn + in_ * 8 + 2 * t4;
            *(float2*)(C + (size_t)mA * N + n) =
                make_float2(acc[im][in_][0], acc[im][in_][1]);
            *(float2*)(C + (size_t)(mA + 8) * N + n) =
                make_float2(acc[im][in_][2], acc[im][in_][3]);
        }
    }
}

// ---------------------------------------------------------------------------
// RoPE: reads fp32 Q/K, writes half Qh (pre-scaled by 1/sqrt(DH)) and Kh.
// Each thread handles 2 consecutive dh in [0,64) -> half2 stores.
// ---------------------------------------------------------------------------
__global__ void rope_half(const float* __restrict__ Qf,
                          const float* __restrict__ Kf,
                          __half* __restrict__ Qh, __half* __restrict__ Kh,
                          const float* __restrict__ cosp,
                          const float* __restrict__ sinp) {
    int i = blockIdx.x * blockDim.x + threadIdx.x;
    const int total = Bc * Sc * Hc * 32;
    if (i >= total) return;
    int d2 = (i & 31) * 2;            // 0..62
    int h  = (i >> 5) & (Hc - 1);
    int bs = i >> 9;
    int s  = bs & (Sc - 1);
    size_t base = (size_t)bs * Dc + h * DHc;

    const float* src = blockIdx.y ? Kf : Qf;
    float2 x1 = *(const float2*)(src + base + d2);
    float2 x2 = *(const float2*)(src + base + d2 + 64);
    float2 c  = *(const float2*)(cosp + s * DHc + d2);
    float2 sn = *(const float2*)(sinp + s * DHc + d2);

    float r1x = x1.x * c.x - x2.x * sn.x;
    float r1y = x1.y * c.y - x2.y * sn.y;
    float r2x = x2.x * c.x + x1.x * sn.x;
    float r2y = x2.y * c.y + x1.y * sn.y;

    if (blockIdx.y == 0) {
        const float scale = 0.08838834764831845f;
        r1x *= scale; r1y *= scale; r2x *= scale; r2y *= scale;
    }
    __half* dst = blockIdx.y ? Kh : Qh;
    *(__half2*)(dst + base + d2)      = __floats2half2_rn(r1x, r1y);
    *(__half2*)(dst + base + d2 + 64) = __floats2half2_rn(r2x, r2y);
}

// ---------------------------------------------------------------------------
// Flash attention: QK^T in fp16 mma (half Q/K), softmax fp32, PV in tf32 mma
// (float V). 128 thr / 4 warps; BM=BN=64. Double-buffered K; V load overlaps
// QK compute; K(j+1) load overlaps PV(j). Output written as half.
// ---------------------------------------------------------------------------
constexpr int QSH = 136;   // halves
constexpr int KSH = 136;   // halves
constexpr int VSF = 136;   // floats
constexpr int PSF = 68;    // floats
constexpr int OFF_Q  = 0;
constexpr int OFF_K0 = OFF_Q  + 64 * QSH * 2;        // 17408
constexpr int OFF_K1 = OFF_K0 + 64 * KSH * 2;        // 34816
constexpr int OFF_V  = OFF_K1 + 64 * KSH * 2;        // 52224
constexpr int OFF_P  = OFF_V  + 64 * VSF * 4;        // 87040
constexpr int FL_SMEM_B = OFF_P + 64 * PSF * 4;      // 104448

__global__ void __launch_bounds__(128) flash_tc(const __half* __restrict__ Q,
                                                const __half* __restrict__ K,
                                                const float* __restrict__ V,
                                                __half* __restrict__ O) {
    extern __shared__ char smraw[];
    __half* sQ   = (__half*)(smraw + OFF_Q);
    __half* sK0  = (__half*)(smraw + OFF_K0);
    __half* sK1  = (__half*)(smraw + OFF_K1);
    float*  sV   = (float*)(smraw + OFF_V);
    float*  sP   = (float*)(smraw + OFF_P);
    const uint32_t sQ_u  = (uint32_t)__cvta_generic_to_shared(sQ);
    const uint32_t sK0_u = (uint32_t)__cvta_generic_to_shared(sK0);
    const uint32_t sK1_u = (uint32_t)__cvta_generic_to_shared(sK1);
    const uint32_t sV_u  = (uint32_t)__cvta_generic_to_shared(sV);

    const int tid  = threadIdx.x;
    const int wid  = tid >> 5;
    const int lane = tid & 31;
    const int gp   = lane >> 2;
    const int t4   = lane & 3;
    const int qb   = blockIdx.x;
    const int bh   = blockIdx.y;
    const int b    = bh >> 4;
    const int h    = bh & (Hc - 1);
    const size_t base = ((size_t)b * Sc) * Dc + (size_t)h * DHc;
    const int q0   = qb * 64;
    const int r0loc = wid * 16 + gp;
    const int r1loc = r0loc + 8;

    // prologue: Q + K0 in group 0, V0 in group 1
    {
#pragma unroll
        for (int p = 0; p < 8; p++) {       // Q: 64 rows x 16 segs (8 halves)
            int idx = tid + p * 128;
            int r = idx >> 4, sg = (idx & 15) * 8;
            uint32_t dst = sQ_u + (uint32_t)((r * QSH + sg) * 2);
            CP_ASYNC16(dst, Q + base + (size_t)(q0 + r) * Dc + sg);
        }
#pragma unroll
        for (int p = 0; p < 8; p++) {       // K0
            int idx = tid + p * 128;
            int r = idx >> 4, sg = (idx & 15) * 8;
            uint32_t dst = sK0_u + (uint32_t)((r * KSH + sg) * 2);
            CP_ASYNC16(dst, K + base + (size_t)r * Dc + sg);
        }
        asm volatile("cp.async.commit_group;\n");
#pragma unroll
        for (int p = 0; p < 16; p++) {      // V0: 64 rows x 32 segs (4 floats)
            int idx = tid + p * 128;
            int r = idx >> 5, c4 = (idx & 31) * 4;
            uint32_t dst = sV_u + (uint32_t)((r * VSF + c4) * 4);
            CP_ASYNC16(dst, V + base + (size_t)r * Dc + c4);
        }
        asm volatile("cp.async.commit_group;\n");
    }

    float o[16][4];
#pragma unroll
    for (int n = 0; n < 16; n++)
#pragma unroll
        for (int r = 0; r < 4; r++) o[n][r] = 0.f;
    float m0 = -1e30f, m1 = -1e30f, l0 = 0.f, l1 = 0.f;

    for (int j = 0; j <= qb; ++j) {
        const __half* sKc = (j & 1) ? sK1 : sK0;
        const uint32_t sKn_u = (j & 1) ? sK0_u : sK1_u;

        // K_j (and Q on j=0) ready; V_j may still be in flight
        asm volatile("cp.async.wait_group 1;\n");
        __syncthreads();

        // ---- S = Qs @ K^T  (fp16 mma, 8 k-steps of 16) ----
        float sacc[8][4];
#pragma unroll
        for (int n = 0; n < 8; n++)
#pragma unroll
            for (int r = 0; r < 4; r++) sacc[n][r] = 0.f;

#pragma unroll
        for (int kk8 = 0; kk8 < 8; kk8++) {
            const int kk = kk8 * 16;
            const __half* qa = sQ + r0loc * QSH + kk + 2 * t4;
            uint32_t a0 = ld32h(qa);
            uint32_t a1 = ld32h(qa + 8 * QSH);
            uint32_t a2 = ld32h(qa + 8);
            uint32_t a3 = ld32h(qa + 8 * QSH + 8);
#pragma unroll
            for (int nt = 0; nt < 8; nt++) {
                const __half* kp = sKc + (nt * 8 + gp) * KSH + kk + 2 * t4;
                uint32_t b0 = ld32h(kp);
                uint32_t b1 = ld32h(kp + 8);
                MMA_F16(sacc[nt], a0, a1, a2, a3, b0, b1);
            }
        }

        if (j == qb) {
#pragma unroll
            for (int nt = 0; nt < 8; nt++) {
                int c0 = nt * 8 + 2 * t4;
                if (c0 > r0loc)     sacc[nt][0] = -1e30f;
                if (c0 + 1 > r0loc) sacc[nt][1] = -1e30f;
                if (c0 > r1loc)     sacc[nt][2] = -1e30f;
                if (c0 + 1 > r1loc) sacc[nt][3] = -1e30f;
            }
        }

        // ---- online softmax ----
        float mx0 = -1e30f, mx1 = -1e30f;
#pragma unroll
        for (int nt = 0; nt < 8; nt++) {
            mx0 = fmaxf(mx0, fmaxf(sacc[nt][0], sacc[nt][1]));
            mx1 = fmaxf(mx1, fmaxf(sacc[nt][2], sacc[nt][3]));
        }
        mx0 = fmaxf(mx0, __shfl_xor_sync(0xffffffff, mx0, 1));
        mx0 = fmaxf(mx0, __shfl_xor_sync(0xffffffff, mx0, 2));
        mx1 = fmaxf(mx1, __shfl_xor_sync(0xffffffff, mx1, 1));
        mx1 = fmaxf(mx1, __shfl_xor_sync(0xffffffff, mx1, 2));

        float m0n = fmaxf(m0, mx0);
        float m1n = fmaxf(m1, mx1);
        float corr0 = __expf(m0 - m0n);
        float corr1 = __expf(m1 - m1n);
        m0 = m0n; m1 = m1n;

        float ls0 = 0.f, ls1 = 0.f;
#pragma unroll
        for (int nt = 0; nt < 8; nt++) {
            float p0 = __expf(sacc[nt][0] - m0);
            float p1 = __expf(sacc[nt][1] - m0);
            float p2 = __expf(sacc[nt][2] - m1);
            float p3 = __expf(sacc[nt][3] - m1);
            ls0 += p0 + p1;
            ls1 += p2 + p3;
            int c0 = nt * 8 + 2 * t4;
            *(float2*)(sP + r0loc * PSF + c0) =
                make_float2(rna_tf32(p0), rna_tf32(p1));
            *(float2*)(sP + r1loc * PSF + c0) =
                make_float2(rna_tf32(p2), rna_tf32(p3));
        }
        ls0 += __shfl_xor_sync(0xffffffff, ls0, 1);
        ls0 += __shfl_xor_sync(0xffffffff, ls0, 2);
        ls1 += __shfl_xor_sync(0xffffffff, ls1, 1);
        ls1 += __shfl_xor_sync(0xffffffff, ls1, 2);
        l0 = l0 * corr0 + ls0;
        l1 = l1 * corr1 + ls1;

#pragma unroll
        for (int nt = 0; nt < 16; nt++) {
            o[nt][0] *= corr0; o[nt][1] *= corr0;
            o[nt][2] *= corr1; o[nt][3] *= corr1;
        }

        // prefetch K_{j+1} into the other K buffer (safe: that buffer's last
        // readers finished before this iteration's top-of-loop barrier)
        if (j < qb) {
            const int k0n = (j + 1) * 64;
#pragma unroll
            for (int p = 0; p < 8; p++) {
                int idx = tid + p * 128;
                int r = idx >> 4, sg = (idx & 15) * 8;
                uint32_t dst = sKn_u + (uint32_t)((r * KSH + sg) * 2);
                CP_ASYNC16(dst, K + base + (size_t)(k0n + r) * Dc + sg);
            }
            asm volatile("cp.async.commit_group;\n");
            asm volatile("cp.async.wait_group 1;\n");   // V_j done, K_{j+1} flying
        } else {
            asm volatile("cp.async.wait_group 0;\n");
        }
        __syncthreads();   // P visible to all + V ready

        // ---- O += P @ V  (tf32 mma) ----
#pragma unroll
        for (int kk4 = 0; kk4 < 8; kk4++) {
            const int kb = kk4 * 8;
            const float* pa = sP + r0loc * PSF + kb + t4;
            uint32_t a0 = __float_as_uint(pa[0]);
            uint32_t a1 = __float_as_uint(pa[8 * PSF]);
            uint32_t a2 = __float_as_uint(pa[4]);
            uint32_t a3 = __float_as_uint(pa[8 * PSF + 4]);
#pragma unroll
            for (int nt = 0; nt < 16; nt++) {
                const float* vp = sV + (kb + t4) * VSF + nt * 8 + gp;
                uint32_t b0 = __float_as_uint(vp[0]);
                uint32_t b1 = __float_as_uint(vp[4 * VSF]);
                MMA_TF32(o[nt], a0, a1, a2, a3, b0, b1);
            }
        }
        __syncthreads();   // all warps done with sV / sP

        if (j < qb) {
            const int k0n = (j + 1) * 64;
#pragma unroll
            for (int p = 0; p < 16; p++) {
                int idx = tid + p * 128;
                int r = idx >> 5, c4 = (idx & 31) * 4;
                uint32_t dst = sV_u + (uint32_t)((r * VSF + c4) * 4);
                CP_ASYNC16(dst, V + base + (size_t)(k0n + r) * Dc + c4);
            }
            asm volatile("cp.async.commit_group;\n");
        }
    }

    // epilogue: normalize, write half (feeds the fp16 O-projection GEMM)
    float inv0 = 1.0f / l0, inv1 = 1.0f / l1;
    const size_t row0 = base + (size_t)(q0 + r0loc) * Dc;
    const size_t row1 = base + (size_t)(q0 + r1loc) * Dc;
#pragma unroll
    for (int nt = 0; nt < 16; nt++) {
        int c0 = nt * 8 + 2 * t4;
        *(__half2*)(O + row0 + c0) =
            __floats2half2_rn(o[nt][0] * inv0, o[nt][1] * inv0);
        *(__half2*)(O + row1 + c0) =
            __floats2half2_rn(o[nt][2] * inv1, o[nt][3] * inv1);
    }
}

// ---------------------------------------------------------------------------
// Launch
// ---------------------------------------------------------------------------
extern "C" void kernel_launch(void* const* d_in, const int* in_sizes, int n_in,
                              void* d_out, int out_size) {
    const float* x    = (const float*)d_in[0];
    const float* cosp = (const float*)d_in[1];
    const float* sinp = (const float*)d_in[2];
    const float* Wq   = (const float*)d_in[3];
    const float* Wk   = (const float*)d_in[4];
    const float* Wv   = (const float*)d_in[5];
    const float* Wo   = (const float*)d_in[6];
    float* out = (float*)d_out;

    float *Qb, *Kb, *Vb;
    __half *xh, *Qh, *Kh, *Ah, *wqh, *wkh, *wvh, *woh;
    cudaGetSymbolAddress((void**)&Qb, g_Q);
    cudaGetSymbolAddress((void**)&Kb, g_K);
    cudaGetSymbolAddress((void**)&Vb, g_V);
    cudaGetSymbolAddress((void**)&xh, g_xh);
    cudaGetSymbolAddress((void**)&Qh, g_Qh);
    cudaGetSymbolAddress((void**)&Kh, g_Kh);
    cudaGetSymbolAddress((void**)&Ah, g_Ah);
    cudaGetSymbolAddress((void**)&wqh, g_wqh);
    cudaGetSymbolAddress((void**)&wkh, g_wkh);
    cudaGetSymbolAddress((void**)&wvh, g_wvh);
    cudaGetSymbolAddress((void**)&woh, g_woh);

    cudaFuncSetAttribute(gemm_f16, cudaFuncAttributeMaxDynamicSharedMemorySize,
                         GEMM_SMEM_B);
    cudaFuncSetAttribute(flash_tc, cudaFuncAttributeMaxDynamicSharedMemorySize,
                         FL_SMEM_B);

    // fp16 conversions of GEMM inputs
    {
        const int nx = Mc * Dc / 4, nw = Dc * Dc / 4;
        cvt_half<<<(nx + 255) / 256, 256>>>(x,  xh,  nx);
        cvt_half<<<(nw + 255) / 256, 256>>>(Wq, wqh, nw);
        cvt_half<<<(nw + 255) / 256, 256>>>(Wk, wkh, nw);
        cvt_half<<<(nw + 255) / 256, 256>>>(Wv, wvh, nw);
        cvt_half<<<(nw + 255) / 256, 256>>>(Wo, woh, nw);
    }

    dim3 ggrid(Dc / 128, Mc / 128);   // (16, 32)

    gemm_f16<<<ggrid, 128, GEMM_SMEM_B>>>(xh, wqh, Qb, Mc, Dc, Dc, 0);
    gemm_f16<<<ggrid, 128, GEMM_SMEM_B>>>(xh, wkh, Kb, Mc, Dc, Dc, 0);
    gemm_f16<<<ggrid, 128, GEMM_SMEM_B>>>(xh, wvh, Vb, Mc, Dc, Dc, 1); // tf32-round V

    // RoPE -> half Qh (scaled), Kh
    {
        int total = Bc * Sc * Hc * 32;
        dim3 rgrid((total + 255) / 256, 2);
        rope_half<<<rgrid, 256>>>(Qb, Kb, Qh, Kh, cosp, sinp);
    }

    // flash attention (half output)
    {
        dim3 fgrid(Sc / 64, Bc * Hc);   // (32, 32)
        flash_tc<<<fgrid, 128, FL_SMEM_B>>>(Qh, Kh, Vb, Ah);
    }

    // O projection
    gemm_f16<<<ggrid, 128, GEMM_SMEM_B>>>(Ah, woh, out, Mc, Dc, Dc, 0);
}

// round 7
// speedup vs baseline: 8.1052x; 1.2124x over previous
#include <cuda_runtime.h>
#include <cuda_fp16.h>
#include <math.h>
#include <stdint.h>

// Problem constants
constexpr int Bc  = 2;
constexpr int Sc  = 2048;
constexpr int Dc  = 2048;
constexpr int Hc  = 16;
constexpr int DHc = 128;
constexpr int Mc  = Bc * Sc;   // 4096 rows for projections

// ---------------------------------------------------------------------------
// Scratch (device globals: allocation-free per harness rules)
// ---------------------------------------------------------------------------
__device__ float  g_Q [(size_t)Mc * Dc];       // fp32 pre-rope Q
__device__ float  g_K [(size_t)Mc * Dc];       // fp32 pre-rope K
__device__ __half g_Vh [(size_t)Mc * Dc];      // half V (PV mma operand)
__device__ __half g_xh [(size_t)Mc * Dc];
__device__ __half g_Qh [(size_t)Mc * Dc];      // roped + softmax-scaled
__device__ __half g_Kh [(size_t)Mc * Dc];      // roped
__device__ __half g_Ah [(size_t)Mc * Dc];      // attention out (half)
__device__ __half g_wqh[(size_t)Dc * Dc];
__device__ __half g_wkh[(size_t)Dc * Dc];
__device__ __half g_wvh[(size_t)Dc * Dc];
__device__ __half g_woh[(size_t)Dc * Dc];

#define CP_ASYNC16(dst, src) \
    asm volatile("cp.async.cg.shared.global [%0], [%1], 16;\n" :: "r"(dst), "l"(src))

#define MMA_F16(c, a0, a1, a2, a3, b0, b1)                                     \
    asm volatile(                                                              \
        "mma.sync.aligned.m16n8k16.row.col.f32.f16.f16.f32 "                   \
        "{%0,%1,%2,%3}, {%4,%5,%6,%7}, {%8,%9}, {%0,%1,%2,%3};\n"              \
        : "+f"((c)[0]), "+f"((c)[1]), "+f"((c)[2]), "+f"((c)[3])               \
        : "r"(a0), "r"(a1), "r"(a2), "r"(a3), "r"(b0), "r"(b1))

#define LDSM_X4(r0, r1, r2, r3, addr)                                          \
    asm volatile("ldmatrix.sync.aligned.m8n8.x4.shared.b16 {%0,%1,%2,%3}, [%4];" \
        : "=r"(r0), "=r"(r1), "=r"(r2), "=r"(r3) : "r"(addr))

#define LDSM_X4_T(r0, r1, r2, r3, addr)                                        \
    asm volatile("ldmatrix.sync.aligned.m8n8.x4.trans.shared.b16 {%0,%1,%2,%3}, [%4];" \
        : "=r"(r0), "=r"(r1), "=r"(r2), "=r"(r3) : "r"(addr))

// ---------------------------------------------------------------------------
// fp32 -> fp16 conversion (round-to-nearest)
// ---------------------------------------------------------------------------
__global__ void cvt_half(const float* __restrict__ in, __half* __restrict__ out,
                         int n4) {
    int i = blockIdx.x * blockDim.x + threadIdx.x;
    if (i >= n4) return;
    float4 v = *(const float4*)(in + (size_t)i * 4);
    __half2 h01 = __floats2half2_rn(v.x, v.y);
    __half2 h23 = __floats2half2_rn(v.z, v.w);
    uint2 u;
    u.x = *(uint32_t*)&h01;
    u.y = *(uint32_t*)&h23;
    *(uint2*)(out + (size_t)i * 4) = u;
}

// ---------------------------------------------------------------------------
// fp16 mma GEMM:  C[M,N] = A[M,K] @ B[N,K]^T   (row-major, K contiguous)
// BM=BN=128, BK=32 halves, 128 thr = 4 warps (2m x 2n), warp tile 64x64,
// m16n8k16 atoms, ldmatrix fragment loads, cp.async double-buffered,
// smem stride 40 halves (row-bank = 20L mod 32: conflict-free).
// Output fp32 (Cf) or half (Ch).
// ---------------------------------------------------------------------------
constexpr int HST = 40;                               // halves per smem row
constexpr int GEMM_SMEM_B = 2 * 2 * 128 * HST * 2;    // 40960 bytes

__global__ void __launch_bounds__(128) gemm_f16(const __half* __restrict__ A,
                                                const __half* __restrict__ B,
                                                float* __restrict__ Cf,
                                                __half* __restrict__ Ch,
                                                int M, int N, int K) {
    extern __shared__ __half hsm[];
    __half* sA = hsm;                      // [2][128][40]
    __half* sB = hsm + 2 * 128 * HST;      // [2][128][40]

    const int tid  = threadIdx.x;
    const int wid  = tid >> 5;
    const int lane = tid & 31;
    const int wm = (wid & 1) * 64;
    const int wn = (wid >> 1) * 64;
    const int gp = lane >> 2;
    const int t4 = lane & 3;
    const int m0 = blockIdx.y * 128;
    const int n0 = blockIdx.x * 128;

    // ldmatrix lane -> (row, col) mapping
    const int arow = (lane & 7) + ((lane >> 3) & 1) * 8;  // A/B non-trans x4
    const int acol = (lane >> 4) * 8;
    const int brow = (lane & 7) + (lane >> 4) * 8;
    const int bcol = ((lane >> 3) & 1) * 8;

    // loader: 128 rows x 4 segs (8 halves = 16B) per matrix; 4 passes/thread
    const int lrow = tid >> 2;         // 0..31
    const int lseg = tid & 3;          // 0..3
    const __half* Ag = A + (size_t)(m0 + lrow) * K + lseg * 8;
    const __half* Bg = B + (size_t)(n0 + lrow) * K + lseg * 8;

    const uint32_t sA_u = (uint32_t)__cvta_generic_to_shared(sA);
    const uint32_t sB_u = (uint32_t)__cvta_generic_to_shared(sB);

    float acc[4][8][4];
#pragma unroll
    for (int im = 0; im < 4; im++)
#pragma unroll
        for (int in_ = 0; in_ < 8; in_++)
#pragma unroll
            for (int r = 0; r < 4; r++) acc[im][in_][r] = 0.f;

    const int nt = K / 32;

    {
#pragma unroll
        for (int p = 0; p < 4; p++) {
            int row = lrow + p * 32;
            uint32_t da = sA_u + (uint32_t)((row * HST + lseg * 8) * 2);
            uint32_t db = sB_u + (uint32_t)((row * HST + lseg * 8) * 2);
            CP_ASYNC16(da, Ag + (size_t)p * 32 * K);
            CP_ASYNC16(db, Bg + (size_t)p * 32 * K);
        }
        asm volatile("cp.async.commit_group;\n");
    }

    for (int kt = 0; kt < nt; kt++) {
        const int cur = kt & 1;
        if (kt + 1 < nt) {
            const int nb = cur ^ 1;
            const int k0 = (kt + 1) * 32;
#pragma unroll
            for (int p = 0; p < 4; p++) {
                int row = lrow + p * 32;
                uint32_t da = sA_u + (uint32_t)((((nb * 128) + row) * HST + lseg * 8) * 2);
                uint32_t db = sB_u + (uint32_t)((((nb * 128) + row) * HST + lseg * 8) * 2);
                CP_ASYNC16(da, Ag + (size_t)p * 32 * K + k0);
                CP_ASYNC16(db, Bg + (size_t)p * 32 * K + k0);
            }
            asm volatile("cp.async.commit_group;\n");
            asm volatile("cp.async.wait_group 1;\n");
        } else {
            asm volatile("cp.async.wait_group 0;\n");
        }
        __syncthreads();

        const uint32_t cA_u = sA_u + (uint32_t)(cur * 128 * HST * 2);
        const uint32_t cB_u = sB_u + (uint32_t)(cur * 128 * HST * 2);

#pragma unroll
        for (int ks = 0; ks < 2; ks++) {
            const int kk = ks * 16;
            uint32_t af[4][4];
#pragma unroll
            for (int im = 0; im < 4; im++) {
                uint32_t addr = cA_u +
                    (uint32_t)(((wm + im * 16 + arow) * HST + kk + acol) * 2);
                LDSM_X4(af[im][0], af[im][1], af[im][2], af[im][3], addr);
            }
            uint32_t bf[8][2];
#pragma unroll
            for (int j2 = 0; j2 < 4; j2++) {
                uint32_t addr = cB_u +
                    (uint32_t)(((wn + j2 * 16 + brow) * HST + kk + bcol) * 2);
                LDSM_X4(bf[2 * j2][0], bf[2 * j2][1],
                        bf[2 * j2 + 1][0], bf[2 * j2 + 1][1], addr);
            }
#pragma unroll
            for (int im = 0; im < 4; im++)
#pragma unroll
                for (int in_ = 0; in_ < 8; in_++)
                    MMA_F16(acc[im][in_], af[im][0], af[im][1], af[im][2],
                            af[im][3], bf[in_][0], bf[in_][1]);
        }
        __syncthreads();
    }

#pragma unroll
    for (int im = 0; im < 4; im++) {
        const int mA = m0 + wm + im * 16 + gp;
#pragma unroll
        for (int in_ = 0; in_ < 8; in_++) {
            const int n = n0 + wn + in_ * 8 + 2 * t4;
            if (Ch) {
                *(__half2*)(Ch + (size_t)mA * N + n) =
                    __floats2half2_rn(acc[im][in_][0], acc[im][in_][1]);
                *(__half2*)(Ch + (size_t)(mA + 8) * N + n) =
                    __floats2half2_rn(acc[im][in_][2], acc[im][in_][3]);
            } else {
                *(float2*)(Cf + (size_t)mA * N + n) =
                    make_float2(acc[im][in_][0], acc[im][in_][1]);
                *(float2*)(Cf + (size_t)(mA + 8) * N + n) =
                    make_float2(acc[im][in_][2], acc[im][in_][3]);
            }
        }
    }
}

// ---------------------------------------------------------------------------
// RoPE: reads fp32 Q/K, writes half Qh (pre-scaled by 1/sqrt(DH)) and Kh.
// ---------------------------------------------------------------------------
__global__ void rope_half(const float* __restrict__ Qf,
                          const float* __restrict__ Kf,
                          __half* __restrict__ Qh, __half* __restrict__ Kh,
                          const float* __restrict__ cosp,
                          const float* __restrict__ sinp) {
    int i = blockIdx.x * blockDim.x + threadIdx.x;
    const int total = Bc * Sc * Hc * 32;
    if (i >= total) return;
    int d2 = (i & 31) * 2;            // 0..62
    int h  = (i >> 5) & (Hc - 1);
    int bs = i >> 9;
    int s  = bs & (Sc - 1);
    size_t base = (size_t)bs * Dc + h * DHc;

    const float* src = blockIdx.y ? Kf : Qf;
    float2 x1 = *(const float2*)(src + base + d2);
    float2 x2 = *(const float2*)(src + base + d2 + 64);
    float2 c  = *(const float2*)(cosp + s * DHc + d2);
    float2 sn = *(const float2*)(sinp + s * DHc + d2);

    float r1x = x1.x * c.x - x2.x * sn.x;
    float r1y = x1.y * c.y - x2.y * sn.y;
    float r2x = x2.x * c.x + x1.x * sn.x;
    float r2y = x2.y * c.y + x1.y * sn.y;

    if (blockIdx.y == 0) {
        const float scale = 0.08838834764831845f;
        r1x *= scale; r1y *= scale; r2x *= scale; r2y *= scale;
    }
    __half* dst = blockIdx.y ? Kh : Qh;
    *(__half2*)(dst + base + d2)      = __floats2half2_rn(r1x, r1y);
    *(__half2*)(dst + base + d2 + 64) = __floats2half2_rn(r2x, r2y);
}

// ---------------------------------------------------------------------------
// Flash attention: all-fp16 mma (QK^T and PV), fp32 softmax/accumulators.
// 128 thr / 4 warps; BM=BN=64. ldmatrix fragment loads; ldmatrix.trans for V.
// Double-buffered K; V load overlaps QK compute; K(j+1) overlaps PV(j).
// ---------------------------------------------------------------------------
constexpr int QSH = 136;   // halves
constexpr int KSH = 136;   // halves
constexpr int VSH = 136;   // halves
constexpr int PSH = 72;    // halves
constexpr int OFF_Q  = 0;
constexpr int OFF_K0 = OFF_Q  + 64 * QSH * 2;        // 17408
constexpr int OFF_K1 = OFF_K0 + 64 * KSH * 2;        // 34816
constexpr int OFF_V  = OFF_K1 + 64 * KSH * 2;        // 52224
constexpr int OFF_P  = OFF_V  + 64 * VSH * 2;        // 69632
constexpr int FL_SMEM_B = OFF_P + 64 * PSH * 2;      // 78848

__global__ void __launch_bounds__(128) flash_tc(const __half* __restrict__ Q,
                                                const __half* __restrict__ K,
                                                const __half* __restrict__ V,
                                                __half* __restrict__ O) {
    extern __shared__ char smraw[];
    __half* sP = (__half*)(smraw + OFF_P);
    const uint32_t sQ_u  = (uint32_t)__cvta_generic_to_shared(smraw + OFF_Q);
    const uint32_t sK0_u = (uint32_t)__cvta_generic_to_shared(smraw + OFF_K0);
    const uint32_t sK1_u = (uint32_t)__cvta_generic_to_shared(smraw + OFF_K1);
    const uint32_t sV_u  = (uint32_t)__cvta_generic_to_shared(smraw + OFF_V);
    const uint32_t sP_u  = (uint32_t)__cvta_generic_to_shared(sP);

    const int tid  = threadIdx.x;
    const int wid  = tid >> 5;
    const int lane = tid & 31;
    const int gp   = lane >> 2;
    const int t4   = lane & 3;
    const int qb   = blockIdx.x;
    const int bh   = blockIdx.y;
    const int b    = bh >> 4;
    const int h    = bh & (Hc - 1);
    const size_t base = ((size_t)b * Sc) * Dc + (size_t)h * DHc;
    const int q0   = qb * 64;
    const int wrow = wid * 16;
    const int r0loc = wrow + gp;
    const int r1loc = r0loc + 8;

    // ldmatrix lane mappings
    const int arow = (lane & 7) + ((lane >> 3) & 1) * 8;   // non-trans x4
    const int acol = (lane >> 4) * 8;
    const int brow = (lane & 7) + (lane >> 4) * 8;
    const int bcol = ((lane >> 3) & 1) * 8;
    const int vrow = (lane & 7) + ((lane >> 3) & 1) * 8;   // trans x4 (k rows)
    const int vcol = (lane >> 4) * 8;                      // n col offset

    // prologue: Q + K0 in group 0, V0 in group 1
    {
#pragma unroll
        for (int p = 0; p < 8; p++) {       // Q: 64 rows x 16 segs (8 halves)
            int idx = tid + p * 128;
            int r = idx >> 4, sg = (idx & 15) * 8;
            CP_ASYNC16(sQ_u + (uint32_t)((r * QSH + sg) * 2),
                       Q + base + (size_t)(q0 + r) * Dc + sg);
        }
#pragma unroll
        for (int p = 0; p < 8; p++) {       // K0
            int idx = tid + p * 128;
            int r = idx >> 4, sg = (idx & 15) * 8;
            CP_ASYNC16(sK0_u + (uint32_t)((r * KSH + sg) * 2),
                       K + base + (size_t)r * Dc + sg);
        }
        asm volatile("cp.async.commit_group;\n");
#pragma unroll
        for (int p = 0; p < 8; p++) {       // V0
            int idx = tid + p * 128;
            int r = idx >> 4, sg = (idx & 15) * 8;
            CP_ASYNC16(sV_u + (uint32_t)((r * VSH + sg) * 2),
                       V + base + (size_t)r * Dc + sg);
        }
        asm volatile("cp.async.commit_group;\n");
    }

    float o[16][4];
#pragma unroll
    for (int n = 0; n < 16; n++)
#pragma unroll
        for (int r = 0; r < 4; r++) o[n][r] = 0.f;
    float m0 = -1e30f, m1 = -1e30f, l0 = 0.f, l1 = 0.f;

    for (int j = 0; j <= qb; ++j) {
        const uint32_t sKc_u = (j & 1) ? sK1_u : sK0_u;
        const uint32_t sKn_u = (j & 1) ? sK0_u : sK1_u;

        asm volatile("cp.async.wait_group 1;\n");   // K_j (and Q) ready
        __syncthreads();

        // ---- S = Qs @ K^T  (fp16 mma, ldmatrix frags) ----
        float sacc[8][4];
#pragma unroll
        for (int n = 0; n < 8; n++)
#pragma unroll
            for (int r = 0; r < 4; r++) sacc[n][r] = 0.f;

#pragma unroll
        for (int kk8 = 0; kk8 < 8; kk8++) {
            const int kk = kk8 * 16;
            uint32_t a0, a1, a2, a3;
            LDSM_X4(a0, a1, a2, a3,
                    sQ_u + (uint32_t)(((wrow + arow) * QSH + kk + acol) * 2));
            uint32_t bf[8][2];
#pragma unroll
            for (int j2 = 0; j2 < 4; j2++) {
                LDSM_X4(bf[2 * j2][0], bf[2 * j2][1],
                        bf[2 * j2 + 1][0], bf[2 * j2 + 1][1],
                        sKc_u + (uint32_t)(((j2 * 16 + brow) * KSH + kk + bcol) * 2));
            }
#pragma unroll
            for (int nt = 0; nt < 8; nt++)
                MMA_F16(sacc[nt], a0, a1, a2, a3, bf[nt][0], bf[nt][1]);
        }

        if (j == qb) {
#pragma unroll
            for (int nt = 0; nt < 8; nt++) {
                int c0 = nt * 8 + 2 * t4;
                if (c0 > r0loc)     sacc[nt][0] = -1e30f;
                if (c0 + 1 > r0loc) sacc[nt][1] = -1e30f;
                if (c0 > r1loc)     sacc[nt][2] = -1e30f;
                if (c0 + 1 > r1loc) sacc[nt][3] = -1e30f;
            }
        }

        // ---- online softmax ----
        float mx0 = -1e30f, mx1 = -1e30f;
#pragma unroll
        for (int nt = 0; nt < 8; nt++) {
            mx0 = fmaxf(mx0, fmaxf(sacc[nt][0], sacc[nt][1]));
            mx1 = fmaxf(mx1, fmaxf(sacc[nt][2], sacc[nt][3]));
        }
        mx0 = fmaxf(mx0, __shfl_xor_sync(0xffffffff, mx0, 1));
        mx0 = fmaxf(mx0, __shfl_xor_sync(0xffffffff, mx0, 2));
        mx1 = fmaxf(mx1, __shfl_xor_sync(0xffffffff, mx1, 1));
        mx1 = fmaxf(mx1, __shfl_xor_sync(0xffffffff, mx1, 2));

        float m0n = fmaxf(m0, mx0);
        float m1n = fmaxf(m1, mx1);
        float corr0 = __expf(m0 - m0n);
        float corr1 = __expf(m1 - m1n);
        m0 = m0n; m1 = m1n;

        float ls0 = 0.f, ls1 = 0.f;
#pragma unroll
        for (int nt = 0; nt < 8; nt++) {
            float p0 = __expf(sacc[nt][0] - m0);
            float p1 = __expf(sacc[nt][1] - m0);
            float p2 = __expf(sacc[nt][2] - m1);
            float p3 = __expf(sacc[nt][3] - m1);
            ls0 += p0 + p1;
            ls1 += p2 + p3;
            int c0 = nt * 8 + 2 * t4;
            *(__half2*)(sP + r0loc * PSH + c0) = __floats2half2_rn(p0, p1);
            *(__half2*)(sP + r1loc * PSH + c0) = __floats2half2_rn(p2, p3);
        }
        ls0 += __shfl_xor_sync(0xffffffff, ls0, 1);
        ls0 += __shfl_xor_sync(0xffffffff, ls0, 2);
        ls1 += __shfl_xor_sync(0xffffffff, ls1, 1);
        ls1 += __shfl_xor_sync(0xffffffff, ls1, 2);
        l0 = l0 * corr0 + ls0;
        l1 = l1 * corr1 + ls1;

#pragma unroll
        for (int nt = 0; nt < 16; nt++) {
            o[nt][0] *= corr0; o[nt][1] *= corr0;
            o[nt][2] *= corr1; o[nt][3] *= corr1;
        }

        // prefetch K_{j+1}
        if (j < qb) {
            const int k0n = (j + 1) * 64;
#pragma unroll
            for (int p = 0; p < 8; p++) {
                int idx = tid + p * 128;
                int r = idx >> 4, sg = (idx & 15) * 8;
                CP_ASYNC16(sKn_u + (uint32_t)((r * KSH + sg) * 2),
                           K + base + (size_t)(k0n + r) * Dc + sg);
            }
            asm volatile("cp.async.commit_group;\n");
            asm volatile("cp.async.wait_group 1;\n");   // V_j done
        } else {
            asm volatile("cp.async.wait_group 0;\n");
        }
        __syncthreads();   // P visible + V ready

        // ---- O += P @ V  (fp16 mma; V via ldmatrix.trans) ----
#pragma unroll
        for (int ks = 0; ks < 4; ks++) {
            const int kk = ks * 16;
            uint32_t a0, a1, a2, a3;
            LDSM_X4(a0, a1, a2, a3,
                    sP_u + (uint32_t)(((wrow + arow) * PSH + kk + acol) * 2));
#pragma unroll
            for (int j2 = 0; j2 < 8; j2++) {
                uint32_t b00, b01, b10, b11;
                LDSM_X4_T(b00, b01, b10, b11,
                    sV_u + (uint32_t)(((kk + vrow) * VSH + j2 * 16 + vcol) * 2));
                MMA_F16(o[2 * j2],     a0, a1, a2, a3, b00, b01);
                MMA_F16(o[2 * j2 + 1], a0, a1, a2, a3, b10, b11);
            }
        }
        __syncthreads();   // all warps done with sV / sP

        if (j < qb) {
            const int k0n = (j + 1) * 64;
#pragma unroll
            for (int p = 0; p < 8; p++) {
                int idx = tid + p * 128;
                int r = idx >> 4, sg = (idx & 15) * 8;
                CP_ASYNC16(sV_u + (uint32_t)((r * VSH + sg) * 2),
                           V + base + (size_t)(k0n + r) * Dc + sg);
            }
            asm volatile("cp.async.commit_group;\n");
        }
    }

    // epilogue: normalize, write half (feeds the fp16 O-projection GEMM)
    float inv0 = 1.0f / l0, inv1 = 1.0f / l1;
    const size_t row0 = base + (size_t)(q0 + r0loc) * Dc;
    const size_t row1 = base + (size_t)(q0 + r1loc) * Dc;
#pragma unroll
    for (int nt = 0; nt < 16; nt++) {
        int c0 = nt * 8 + 2 * t4;
        *(__half2*)(O + row0 + c0) =
            __floats2half2_rn(o[nt][0] * inv0, o[nt][1] * inv0);
        *(__half2*)(O + row1 + c0) =
            __floats2half2_rn(o[nt][2] * inv1, o[nt][3] * inv1);
    }
}

// ---------------------------------------------------------------------------
// Launch
// ---------------------------------------------------------------------------
extern "C" void kernel_launch(void* const* d_in, const int* in_sizes, int n_in,
                              void* d_out, int out_size) {
    const float* x    = (const float*)d_in[0];
    const float* cosp = (const float*)d_in[1];
    const float* sinp = (const float*)d_in[2];
    const float* Wq   = (const float*)d_in[3];
    const float* Wk   = (const float*)d_in[4];
    const float* Wv   = (const float*)d_in[5];
    const float* Wo   = (const float*)d_in[6];
    float* out = (float*)d_out;

    float *Qb, *Kb;
    __half *Vh, *xh, *Qh, *Kh, *Ah, *wqh, *wkh, *wvh, *woh;
    cudaGetSymbolAddress((void**)&Qb, g_Q);
    cudaGetSymbolAddress((void**)&Kb, g_K);
    cudaGetSymbolAddress((void**)&Vh, g_Vh);
    cudaGetSymbolAddress((void**)&xh, g_xh);
    cudaGetSymbolAddress((void**)&Qh, g_Qh);
    cudaGetSymbolAddress((void**)&Kh, g_Kh);
    cudaGetSymbolAddress((void**)&Ah, g_Ah);
    cudaGetSymbolAddress((void**)&wqh, g_wqh);
    cudaGetSymbolAddress((void**)&wkh, g_wkh);
    cudaGetSymbolAddress((void**)&wvh, g_wvh);
    cudaGetSymbolAddress((void**)&woh, g_woh);

    cudaFuncSetAttribute(gemm_f16, cudaFuncAttributeMaxDynamicSharedMemorySize,
                         GEMM_SMEM_B);
    cudaFuncSetAttribute(flash_tc, cudaFuncAttributeMaxDynamicSharedMemorySize,
                         FL_SMEM_B);

    // fp16 conversions of GEMM inputs
    {
        const int nx = Mc * Dc / 4, nw = Dc * Dc / 4;
        cvt_half<<<(nx + 255) / 256, 256>>>(x,  xh,  nx);
        cvt_half<<<(nw + 255) / 256, 256>>>(Wq, wqh, nw);
        cvt_half<<<(nw + 255) / 256, 256>>>(Wk, wkh, nw);
        cvt_half<<<(nw + 255) / 256, 256>>>(Wv, wvh, nw);
        cvt_half<<<(nw + 255) / 256, 256>>>(Wo, woh, nw);
    }

    dim3 ggrid(Dc / 128, Mc / 128);   // (16, 32)

    gemm_f16<<<ggrid, 128, GEMM_SMEM_B>>>(xh, wqh, Qb, nullptr, Mc, Dc, Dc);
    gemm_f16<<<ggrid, 128, GEMM_SMEM_B>>>(xh, wkh, Kb, nullptr, Mc, Dc, Dc);
    gemm_f16<<<ggrid, 128, GEMM_SMEM_B>>>(xh, wvh, nullptr, Vh, Mc, Dc, Dc);

    // RoPE -> half Qh (scaled), Kh
    {
        int total = Bc * Sc * Hc * 32;
        dim3 rgrid((total + 255) / 256, 2);
        rope_half<<<rgrid, 256>>>(Qb, Kb, Qh, Kh, cosp, sinp);
    }

    // flash attention (half in, half out)
    {
        dim3 fgrid(Sc / 64, Bc * Hc);   // (32, 32)
        flash_tc<<<fgrid, 128, FL_SMEM_B>>>(Qh, Kh, Vh, Ah);
    }

    // O projection (fp32 out)
    gemm_f16<<<ggrid, 128, GEMM_SMEM_B>>>(Ah, woh, out, nullptr, Mc, Dc, Dc);
}